// round 7
// baseline (speedup 1.0000x reference)
#include <cuda_runtime.h>
#include <cuda_bf16.h>
#include <math.h>

#define NN 50000
#define EE 800000
#define ET (EE + NN)
#define F1 128
#define C2 64
#define NEG 0.2f

#define SCAN_B 196                       // ceil(50000/256)
#define CHUNK 4

// ---------------- scratch ----------------------------------------------------
__device__ int    g_is64;
__device__ int    g_src [ET];
__device__ int    g_dst [ET];
__device__ int    g_row [NN + 1];
__device__ int    g_wpos[NN];
__device__ int    g_bsum[SCAN_B];
__device__ int    g_csrc[ET];
__device__ int    g_tick1;
__device__ int    g_tick2;

__device__ float  g_h1  [NN * F1];
__device__ float  g_h1e [NN * F1];
__device__ float4 g_as1 [NN];
__device__ float4 g_ad1 [NN];

__device__ float  g_h2  [NN * C2];
__device__ float  g_as2 [NN];
__device__ float  g_ad2 [NN];

__device__ __forceinline__ float lrelu(float v) { return v > 0.0f ? v : NEG * v; }

// ---------------- packed f32x2 helpers ----------------------------------------
__device__ __forceinline__ unsigned long long fma2(unsigned long long a,
                                                   unsigned long long b,
                                                   unsigned long long c) {
    unsigned long long d;
    asm("fma.rn.f32x2 %0, %1, %2, %3;" : "=l"(d) : "l"(a), "l"(b), "l"(c));
    return d;
}
__device__ __forceinline__ unsigned long long pack2(float lo, float hi) {
    unsigned long long r;
    asm("mov.b64 %0, {%1, %2};" : "=l"(r) : "f"(lo), "f"(hi));
    return r;
}
__device__ __forceinline__ float sum2(unsigned long long v) {
    float lo, hi;
    asm("mov.b64 {%0, %1}, %2;" : "=f"(lo), "=f"(hi) : "l"(v));
    return lo + hi;
}

// ---------------- zero counters + dtype detect ---------------------------------
__global__ void zero_detect_kernel(const void* __restrict__ ei) {
    int i = blockIdx.x * blockDim.x + threadIdx.x;
    if (i < NN) g_wpos[i] = 0;
    if (i == 0) { g_tick1 = 0; g_tick2 = 0; }
    if (blockIdx.x == 0) {
        const unsigned long long* p = (const unsigned long long*)ei;
        int bad = (p[threadIdx.x] >= (unsigned long long)NN) ? 1 : 0;
        int anybad = __syncthreads_or(bad);
        if (threadIdx.x == 0) g_is64 = anybad ? 0 : 1;
    }
}

__global__ void convert_hist_kernel(const void* __restrict__ ei) {
    int e = blockIdx.x * blockDim.x + threadIdx.x;
    if (e >= ET) return;
    int s, d;
    if (e >= EE) s = d = e - EE;
    else if (g_is64) {
        s = (int)((const long long*)ei)[e];
        d = (int)((const long long*)ei)[EE + e];
    } else {
        s = ((const int*)ei)[e];
        d = ((const int*)ei)[EE + e];
    }
    g_src[e] = s;
    g_dst[e] = d;
    atomicAdd(&g_wpos[d], 1);
}

// ---------------- scan ----------------------------------------------------------
__device__ __forceinline__ int block_excl_scan(int v, int t, int* total) {
    __shared__ int wsum[8];
    int lane = t & 31, w = t >> 5;
    int inc = v;
#pragma unroll
    for (int o = 1; o < 32; o <<= 1) {
        int u = __shfl_up_sync(0xffffffffu, inc, o);
        if (lane >= o) inc += u;
    }
    if (lane == 31) wsum[w] = inc;
    __syncthreads();
    if (w == 0) {
        int ws = (lane < 8) ? wsum[lane] : 0;
#pragma unroll
        for (int o = 1; o < 8; o <<= 1) {
            int u = __shfl_up_sync(0xffffffffu, ws, o);
            if (lane >= o) ws += u;
        }
        if (lane < 8) wsum[lane] = ws;
    }
    __syncthreads();
    int base = (w > 0) ? wsum[w - 1] : 0;
    *total = wsum[7];
    return base + inc - v;
}

__global__ void scan1_kernel() {
    int t = threadIdx.x;
    int i = blockIdx.x * 256 + t;
    int v = (i < NN) ? g_wpos[i] : 0;
    int total;
    int ex = block_excl_scan(v, t, &total);
    if (i < NN) g_row[i] = ex;
    if (t == 0) g_bsum[blockIdx.x] = total;
}

__global__ void scan3_kernel() {
    __shared__ int ws[8];
    __shared__ int sbase;
    int t = threadIdx.x, b = blockIdx.x;
    int lane = t & 31, w = t >> 5;
    int v = (t < SCAN_B && t < b) ? g_bsum[t] : 0;
#pragma unroll
    for (int o = 16; o; o >>= 1) v += __shfl_xor_sync(0xffffffffu, v, o);
    if (lane == 0) ws[w] = v;
    __syncthreads();
    if (t == 0) {
        int tot = 0;
#pragma unroll
        for (int k = 0; k < 8; k++) tot += ws[k];
        sbase = tot;
    }
    __syncthreads();
    int i = b * 256 + t;
    if (i < NN) {
        int r = g_row[i] + sbase;
        g_row[i] = r;
        g_wpos[i] = r;
    }
    if (i == 0) g_row[NN] = ET;
}

__global__ void scatter_kernel() {
    int e = blockIdx.x * blockDim.x + threadIdx.x;
    if (e >= ET) return;
    int d = g_dst[e];
    int p = atomicAdd(&g_wpos[d], 1);
    g_csrc[p] = g_src[e];
}

// ---------------- gemm1 (f32x2 packed, 16 nodes/block, 128 thr) ---------------
__global__ void __launch_bounds__(128) gemm1_kernel(
        const float* __restrict__ x, const float* __restrict__ W,
        const float* __restrict__ as, const float* __restrict__ ad) {
    __shared__ float xs[16][128];
    int n0 = blockIdx.x * 16;
    int t = threadIdx.x;
    const float4* x4 = (const float4*)(x + n0 * 128);
    float4* xs4 = (float4*)xs;
#pragma unroll
    for (int r = 0; r < 4; r++) xs4[t + r * 128] = x4[t + r * 128];
    __syncthreads();
    int j = t;
    unsigned long long acc2[16];
#pragma unroll
    for (int n = 0; n < 16; n++) acc2[n] = 0ull;
#pragma unroll
    for (int k = 0; k < 128; k += 4) {
        float w0 = W[(k + 0) * 128 + j];
        float w1 = W[(k + 1) * 128 + j];
        float w2 = W[(k + 2) * 128 + j];
        float w3 = W[(k + 3) * 128 + j];
        unsigned long long wp01 = pack2(w0, w1);
        unsigned long long wp23 = pack2(w2, w3);
#pragma unroll
        for (int n = 0; n < 16; n++) {
            const unsigned long long* xp = (const unsigned long long*)&xs[n][k];
            acc2[n] = fma2(xp[0], wp01, acc2[n]);
            acc2[n] = fma2(xp[1], wp23, acc2[n]);
        }
    }
    float asj = as[j], adj = ad[j];
    int h = j >> 5;
#pragma unroll
    for (int n = 0; n < 16; n++) {
        float a = sum2(acc2[n]);
        g_h1[(n0 + n) * 128 + j] = a;
        float vs = a * asj;
        float vd = a * adj;
#pragma unroll
        for (int o = 16; o; o >>= 1) {
            vs += __shfl_xor_sync(0xffffffffu, vs, o);
            vd += __shfl_xor_sync(0xffffffffu, vd, o);
        }
        if ((j & 31) == 0) {
            ((float*)&g_as1[n0 + n])[h] = vs;
            ((float*)&g_ad1[n0 + n])[h] = vd;
        }
    }
}

// ---------------- fused softmax agg layer 1 (ticketed warps) ------------------
__global__ void __launch_bounds__(256) agg1_kernel(const float* __restrict__ b1) {
    int lane = threadIdx.x & 31;
    int h = lane >> 3;
    int co = lane * 4;
    float4 bv = *(const float4*)&b1[co];
    for (;;) {
        int base;
        if (lane == 0) base = atomicAdd(&g_tick1, CHUNK);
        base = __shfl_sync(0xffffffffu, base, 0);
        if (base >= NN) return;
        int end = min(base + CHUNK, NN);
        for (int d = base; d < end; d++) {
            int lo = g_row[d], hi = g_row[d + 1];
            float add = ((const float*)&g_ad1[d])[h];
            float s = 0.0f;
            float4 acc = make_float4(0, 0, 0, 0);
            int i = lo;
            for (; i + 4 <= hi; i += 4) {
                int s0 = g_csrc[i], s1 = g_csrc[i + 1];
                int s2 = g_csrc[i + 2], s3 = g_csrc[i + 3];
                float a0 = ((const float*)&g_as1[s0])[h];
                float a1 = ((const float*)&g_as1[s1])[h];
                float a2 = ((const float*)&g_as1[s2])[h];
                float a3 = ((const float*)&g_as1[s3])[h];
                float4 h0 = *(const float4*)&g_h1[s0 * 128 + co];
                float4 h1 = *(const float4*)&g_h1[s1 * 128 + co];
                float4 h2 = *(const float4*)&g_h1[s2 * 128 + co];
                float4 h3 = *(const float4*)&g_h1[s3 * 128 + co];
                float w0 = __expf(lrelu(a0 + add));
                float w1 = __expf(lrelu(a1 + add));
                float w2 = __expf(lrelu(a2 + add));
                float w3 = __expf(lrelu(a3 + add));
                s += (w0 + w1) + (w2 + w3);
                acc.x = fmaf(w0, h0.x, acc.x); acc.y = fmaf(w0, h0.y, acc.y);
                acc.z = fmaf(w0, h0.z, acc.z); acc.w = fmaf(w0, h0.w, acc.w);
                acc.x = fmaf(w1, h1.x, acc.x); acc.y = fmaf(w1, h1.y, acc.y);
                acc.z = fmaf(w1, h1.z, acc.z); acc.w = fmaf(w1, h1.w, acc.w);
                acc.x = fmaf(w2, h2.x, acc.x); acc.y = fmaf(w2, h2.y, acc.y);
                acc.z = fmaf(w2, h2.z, acc.z); acc.w = fmaf(w2, h2.w, acc.w);
                acc.x = fmaf(w3, h3.x, acc.x); acc.y = fmaf(w3, h3.y, acc.y);
                acc.z = fmaf(w3, h3.z, acc.z); acc.w = fmaf(w3, h3.w, acc.w);
            }
            for (; i < hi; i++) {
                int sc = g_csrc[i];
                float w = __expf(lrelu(((const float*)&g_as1[sc])[h] + add));
                float4 hv = *(const float4*)&g_h1[sc * 128 + co];
                s += w;
                acc.x = fmaf(w, hv.x, acc.x); acc.y = fmaf(w, hv.y, acc.y);
                acc.z = fmaf(w, hv.z, acc.z); acc.w = fmaf(w, hv.w, acc.w);
            }
            float inv = 1.0f / (s + 1e-16f);
            float4 o;
            o.x = acc.x * inv + bv.x;
            o.y = acc.y * inv + bv.y;
            o.z = acc.z * inv + bv.z;
            o.w = acc.w * inv + bv.w;
            o.x = o.x > 0.0f ? o.x : expm1f(o.x);
            o.y = o.y > 0.0f ? o.y : expm1f(o.y);
            o.z = o.z > 0.0f ? o.z : expm1f(o.z);
            o.w = o.w > 0.0f ? o.w : expm1f(o.w);
            *(float4*)&g_h1e[d * 128 + co] = o;
        }
    }
}

// ---------------- gemm2 (f32x2 packed, 16 nodes/block, 64 thr) ----------------
__global__ void __launch_bounds__(64) gemm2_kernel(
        const float* __restrict__ W,
        const float* __restrict__ as, const float* __restrict__ ad) {
    __shared__ float xs[16][128];
    __shared__ float ps[16][2], pd[16][2];
    int n0 = blockIdx.x * 16;
    int t = threadIdx.x;
    const float4* x4 = (const float4*)(g_h1e + n0 * 128);
    float4* xs4 = (float4*)xs;
#pragma unroll
    for (int r = 0; r < 8; r++) xs4[t + r * 64] = x4[t + r * 64];
    __syncthreads();
    int j = t;
    unsigned long long acc2[16];
#pragma unroll
    for (int n = 0; n < 16; n++) acc2[n] = 0ull;
#pragma unroll
    for (int k = 0; k < 128; k += 4) {
        float w0 = W[(k + 0) * 64 + j];
        float w1 = W[(k + 1) * 64 + j];
        float w2 = W[(k + 2) * 64 + j];
        float w3 = W[(k + 3) * 64 + j];
        unsigned long long wp01 = pack2(w0, w1);
        unsigned long long wp23 = pack2(w2, w3);
#pragma unroll
        for (int n = 0; n < 16; n++) {
            const unsigned long long* xp = (const unsigned long long*)&xs[n][k];
            acc2[n] = fma2(xp[0], wp01, acc2[n]);
            acc2[n] = fma2(xp[1], wp23, acc2[n]);
        }
    }
    float asj = as[j], adj = ad[j];
    int w = t >> 5;
#pragma unroll
    for (int n = 0; n < 16; n++) {
        float a = sum2(acc2[n]);
        g_h2[(n0 + n) * 64 + j] = a;
        float vs = a * asj;
        float vd = a * adj;
#pragma unroll
        for (int o = 16; o; o >>= 1) {
            vs += __shfl_xor_sync(0xffffffffu, vs, o);
            vd += __shfl_xor_sync(0xffffffffu, vd, o);
        }
        if ((t & 31) == 0) { ps[n][w] = vs; pd[n][w] = vd; }
    }
    __syncthreads();
    if (t < 16) {
        g_as2[n0 + t] = ps[t][0] + ps[t][1];
        g_ad2[n0 + t] = pd[t][0] + pd[t][1];
    }
}

// ---------------- fused softmax agg layer 2 (ticketed warps) ------------------
__global__ void __launch_bounds__(256) agg2_kernel(
        float* __restrict__ out, const float* __restrict__ b2) {
    int lane = threadIdx.x & 31;
    int co = lane * 2;
    float b2x = b2[co], b2y = b2[co + 1];
    for (;;) {
        int base;
        if (lane == 0) base = atomicAdd(&g_tick2, CHUNK);
        base = __shfl_sync(0xffffffffu, base, 0);
        if (base >= NN) return;
        int end = min(base + CHUNK, NN);
        for (int d = base; d < end; d++) {
            int lo = g_row[d], hi = g_row[d + 1];
            float add = g_ad2[d];
            float s = 0.0f;
            float2 acc = make_float2(0, 0);
            int i = lo;
            for (; i + 4 <= hi; i += 4) {
                int s0 = g_csrc[i], s1 = g_csrc[i + 1];
                int s2 = g_csrc[i + 2], s3 = g_csrc[i + 3];
                float a0 = g_as2[s0], a1 = g_as2[s1];
                float a2 = g_as2[s2], a3 = g_as2[s3];
                float2 h0 = *(const float2*)&g_h2[s0 * 64 + co];
                float2 h1 = *(const float2*)&g_h2[s1 * 64 + co];
                float2 h2 = *(const float2*)&g_h2[s2 * 64 + co];
                float2 h3 = *(const float2*)&g_h2[s3 * 64 + co];
                float w0 = __expf(lrelu(a0 + add));
                float w1 = __expf(lrelu(a1 + add));
                float w2 = __expf(lrelu(a2 + add));
                float w3 = __expf(lrelu(a3 + add));
                s += (w0 + w1) + (w2 + w3);
                acc.x = fmaf(w0, h0.x, acc.x); acc.y = fmaf(w0, h0.y, acc.y);
                acc.x = fmaf(w1, h1.x, acc.x); acc.y = fmaf(w1, h1.y, acc.y);
                acc.x = fmaf(w2, h2.x, acc.x); acc.y = fmaf(w2, h2.y, acc.y);
                acc.x = fmaf(w3, h3.x, acc.x); acc.y = fmaf(w3, h3.y, acc.y);
            }
            for (; i < hi; i++) {
                int sc = g_csrc[i];
                float w = __expf(lrelu(g_as2[sc] + add));
                float2 hv = *(const float2*)&g_h2[sc * 64 + co];
                s += w;
                acc.x = fmaf(w, hv.x, acc.x);
                acc.y = fmaf(w, hv.y, acc.y);
            }
            float inv = 1.0f / (s + 1e-16f);
            float2 o;
            o.x = acc.x * inv + b2x;
            o.y = acc.y * inv + b2y;
            *(float2*)&out[d * 64 + co] = o;
        }
    }
}

// ---------------- launch ---------------------------------------------------------
extern "C" void kernel_launch(void* const* d_in, const int* in_sizes, int n_in,
                              void* d_out, int out_size) {
    const float* x   = (const float*)d_in[0];
    const void*  ei  = d_in[1];
    const float* W1  = (const float*)d_in[2];
    const float* as1 = (const float*)d_in[3];
    const float* ad1 = (const float*)d_in[4];
    const float* b1  = (const float*)d_in[5];
    const float* W2  = (const float*)d_in[6];
    const float* as2 = (const float*)d_in[7];
    const float* ad2 = (const float*)d_in[8];
    const float* b2  = (const float*)d_in[9];
    float*       out = (float*)d_out;

    const int TB = 256;
    auto nb = [](long long n, int tb) { return (int)((n + tb - 1) / tb); };

    // fork: gemm1 (depends only on x/W1) overlaps the CSR build chain
    cudaStream_t s2;
    cudaStreamCreateWithFlags(&s2, cudaStreamNonBlocking);
    cudaEvent_t e1, e2;
    cudaEventCreateWithFlags(&e1, cudaEventDisableTiming);
    cudaEventCreateWithFlags(&e2, cudaEventDisableTiming);

    cudaEventRecord(e1, 0);
    cudaStreamWaitEvent(s2, e1, 0);
    gemm1_kernel<<<NN / 16, 128, 0, s2>>>(x, W1, as1, ad1);
    cudaEventRecord(e2, s2);

    // CSR build on the main stream
    zero_detect_kernel<<<SCAN_B, 256>>>(ei);
    convert_hist_kernel<<<nb(ET, TB), TB>>>(ei);
    scan1_kernel<<<SCAN_B, 256>>>();
    scan3_kernel<<<SCAN_B, 256>>>();
    scatter_kernel<<<nb(ET, TB), TB>>>();

    // join, then the serial tail
    cudaStreamWaitEvent(0, e2, 0);
    agg1_kernel<<<592, 256>>>(b1);
    gemm2_kernel<<<NN / 16, 64>>>(W2, as2, ad2);
    agg2_kernel<<<592, 256>>>(out, b2);
}

// round 8
// speedup vs baseline: 1.1478x; 1.1478x over previous
#include <cuda_runtime.h>
#include <cuda_bf16.h>
#include <math.h>

#define NN 50000
#define EE 800000
#define ET (EE + NN)
#define F1 128
#define C2 64
#define NEG 0.2f

#define SCAN_B 196                       // ceil(50000/256)

// ---------------- scratch ----------------------------------------------------
__device__ int    g_is64;
__device__ int    g_src [ET];
__device__ int    g_dst [ET];
__device__ int    g_row [NN + 1];
__device__ int    g_wpos[NN];
__device__ int    g_bsum[SCAN_B];
__device__ int    g_csrc[ET];

__device__ float  g_h1  [NN * F1];
__device__ float  g_h1e [NN * F1];
__device__ float4 g_as1 [NN];
__device__ float4 g_ad1 [NN];

__device__ float  g_h2  [NN * C2];
__device__ float  g_as2 [NN];
__device__ float  g_ad2 [NN];

__device__ __forceinline__ float lrelu(float v) { return v > 0.0f ? v : NEG * v; }

// ---------------- packed f32x2 helpers ----------------------------------------
__device__ __forceinline__ unsigned long long fma2(unsigned long long a,
                                                   unsigned long long b,
                                                   unsigned long long c) {
    unsigned long long d;
    asm("fma.rn.f32x2 %0, %1, %2, %3;" : "=l"(d) : "l"(a), "l"(b), "l"(c));
    return d;
}
__device__ __forceinline__ unsigned long long pack2(float lo, float hi) {
    unsigned long long r;
    asm("mov.b64 %0, {%1, %2};" : "=l"(r) : "f"(lo), "f"(hi));
    return r;
}
__device__ __forceinline__ float sum2(unsigned long long v) {
    float lo, hi;
    asm("mov.b64 {%0, %1}, %2;" : "=f"(lo), "=f"(hi) : "l"(v));
    return lo + hi;
}

// ---------------- zero counters + dtype detect ---------------------------------
__global__ void zero_detect_kernel(const void* __restrict__ ei) {
    int i = blockIdx.x * blockDim.x + threadIdx.x;
    if (i < NN) g_wpos[i] = 0;
    if (blockIdx.x == 0) {
        const unsigned long long* p = (const unsigned long long*)ei;
        int bad = (p[threadIdx.x] >= (unsigned long long)NN) ? 1 : 0;
        int anybad = __syncthreads_or(bad);
        if (threadIdx.x == 0) g_is64 = anybad ? 0 : 1;
    }
}

__global__ void convert_hist_kernel(const void* __restrict__ ei) {
    int e = blockIdx.x * blockDim.x + threadIdx.x;
    if (e >= ET) return;
    int s, d;
    if (e >= EE) s = d = e - EE;
    else if (g_is64) {
        s = (int)((const long long*)ei)[e];
        d = (int)((const long long*)ei)[EE + e];
    } else {
        s = ((const int*)ei)[e];
        d = ((const int*)ei)[EE + e];
    }
    g_src[e] = s;
    g_dst[e] = d;
    atomicAdd(&g_wpos[d], 1);
}

// ---------------- scan ----------------------------------------------------------
__device__ __forceinline__ int block_excl_scan(int v, int t, int* total) {
    __shared__ int wsum[8];
    int lane = t & 31, w = t >> 5;
    int inc = v;
#pragma unroll
    for (int o = 1; o < 32; o <<= 1) {
        int u = __shfl_up_sync(0xffffffffu, inc, o);
        if (lane >= o) inc += u;
    }
    if (lane == 31) wsum[w] = inc;
    __syncthreads();
    if (w == 0) {
        int ws = (lane < 8) ? wsum[lane] : 0;
#pragma unroll
        for (int o = 1; o < 8; o <<= 1) {
            int u = __shfl_up_sync(0xffffffffu, ws, o);
            if (lane >= o) ws += u;
        }
        if (lane < 8) wsum[lane] = ws;
    }
    __syncthreads();
    int base = (w > 0) ? wsum[w - 1] : 0;
    *total = wsum[7];
    return base + inc - v;
}

__global__ void scan1_kernel() {
    int t = threadIdx.x;
    int i = blockIdx.x * 256 + t;
    int v = (i < NN) ? g_wpos[i] : 0;
    int total;
    int ex = block_excl_scan(v, t, &total);
    if (i < NN) g_row[i] = ex;
    if (t == 0) g_bsum[blockIdx.x] = total;
}

__global__ void scan3_kernel() {
    __shared__ int ws[8];
    __shared__ int sbase;
    int t = threadIdx.x, b = blockIdx.x;
    int lane = t & 31, w = t >> 5;
    int v = (t < SCAN_B && t < b) ? g_bsum[t] : 0;
#pragma unroll
    for (int o = 16; o; o >>= 1) v += __shfl_xor_sync(0xffffffffu, v, o);
    if (lane == 0) ws[w] = v;
    __syncthreads();
    if (t == 0) {
        int tot = 0;
#pragma unroll
        for (int k = 0; k < 8; k++) tot += ws[k];
        sbase = tot;
    }
    __syncthreads();
    int i = b * 256 + t;
    if (i < NN) {
        int r = g_row[i] + sbase;
        g_row[i] = r;
        g_wpos[i] = r;
    }
    if (i == 0) g_row[NN] = ET;
}

__global__ void scatter_kernel() {
    int e = blockIdx.x * blockDim.x + threadIdx.x;
    if (e >= ET) return;
    int d = g_dst[e];
    int p = atomicAdd(&g_wpos[d], 1);
    g_csrc[p] = g_src[e];
}

// ---------------- gemm1 (FFMA2, LDS.128 loads, 16 nodes/block) ----------------
__global__ void __launch_bounds__(128) gemm1_kernel(
        const float* __restrict__ x, const float* __restrict__ W,
        const float* __restrict__ as, const float* __restrict__ ad) {
    __shared__ float xs[16][128];
    int n0 = blockIdx.x * 16;
    int t = threadIdx.x;
    const float4* x4 = (const float4*)(x + n0 * 128);
    float4* xs4 = (float4*)xs;
#pragma unroll
    for (int r = 0; r < 4; r++) xs4[t + r * 128] = x4[t + r * 128];
    __syncthreads();
    int j = t;
    unsigned long long acc2[16];
#pragma unroll
    for (int n = 0; n < 16; n++) acc2[n] = 0ull;
#pragma unroll
    for (int k = 0; k < 128; k += 4) {
        float w0 = W[(k + 0) * 128 + j];
        float w1 = W[(k + 1) * 128 + j];
        float w2 = W[(k + 2) * 128 + j];
        float w3 = W[(k + 3) * 128 + j];
        unsigned long long wp01 = pack2(w0, w1);
        unsigned long long wp23 = pack2(w2, w3);
#pragma unroll
        for (int n = 0; n < 16; n++) {
            float4 xv = *(const float4*)&xs[n][k];      // single LDS.128
            unsigned long long x01 = pack2(xv.x, xv.y); // register-pair views
            unsigned long long x23 = pack2(xv.z, xv.w);
            acc2[n] = fma2(x01, wp01, acc2[n]);
            acc2[n] = fma2(x23, wp23, acc2[n]);
        }
    }
    float asj = as[j], adj = ad[j];
    int h = j >> 5;
#pragma unroll
    for (int n = 0; n < 16; n++) {
        float a = sum2(acc2[n]);
        g_h1[(n0 + n) * 128 + j] = a;
        float vs = a * asj;
        float vd = a * adj;
#pragma unroll
        for (int o = 16; o; o >>= 1) {
            vs += __shfl_xor_sync(0xffffffffu, vs, o);
            vd += __shfl_xor_sync(0xffffffffu, vd, o);
        }
        if ((j & 31) == 0) {
            ((float*)&g_as1[n0 + n])[h] = vs;
            ((float*)&g_ad1[n0 + n])[h] = vd;
        }
    }
}

// ---------------- fused softmax aggregation (max-free), layer 1 --------------
__global__ void __launch_bounds__(256) agg1_kernel(const float* __restrict__ b1) {
    int warp = threadIdx.x >> 5, lane = threadIdx.x & 31;
    int d = blockIdx.x * 8 + warp;
    int lo = g_row[d], hi = g_row[d + 1];
    int h = lane >> 3;
    float add = ((const float*)&g_ad1[d])[h];
    float s = 0.0f;
    float4 acc = make_float4(0, 0, 0, 0);
    int co = lane * 4;
    int i = lo;
    for (; i + 4 <= hi; i += 4) {
        int s0 = g_csrc[i], s1 = g_csrc[i + 1], s2 = g_csrc[i + 2], s3 = g_csrc[i + 3];
        float a0 = ((const float*)&g_as1[s0])[h];
        float a1 = ((const float*)&g_as1[s1])[h];
        float a2 = ((const float*)&g_as1[s2])[h];
        float a3 = ((const float*)&g_as1[s3])[h];
        float4 h0 = *(const float4*)&g_h1[s0 * 128 + co];
        float4 h1 = *(const float4*)&g_h1[s1 * 128 + co];
        float4 h2 = *(const float4*)&g_h1[s2 * 128 + co];
        float4 h3 = *(const float4*)&g_h1[s3 * 128 + co];
        float w0 = __expf(lrelu(a0 + add));
        float w1 = __expf(lrelu(a1 + add));
        float w2 = __expf(lrelu(a2 + add));
        float w3 = __expf(lrelu(a3 + add));
        s += (w0 + w1) + (w2 + w3);
        acc.x = fmaf(w0, h0.x, acc.x); acc.y = fmaf(w0, h0.y, acc.y);
        acc.z = fmaf(w0, h0.z, acc.z); acc.w = fmaf(w0, h0.w, acc.w);
        acc.x = fmaf(w1, h1.x, acc.x); acc.y = fmaf(w1, h1.y, acc.y);
        acc.z = fmaf(w1, h1.z, acc.z); acc.w = fmaf(w1, h1.w, acc.w);
        acc.x = fmaf(w2, h2.x, acc.x); acc.y = fmaf(w2, h2.y, acc.y);
        acc.z = fmaf(w2, h2.z, acc.z); acc.w = fmaf(w2, h2.w, acc.w);
        acc.x = fmaf(w3, h3.x, acc.x); acc.y = fmaf(w3, h3.y, acc.y);
        acc.z = fmaf(w3, h3.z, acc.z); acc.w = fmaf(w3, h3.w, acc.w);
    }
    for (; i < hi; i++) {
        int sc = g_csrc[i];
        float w = __expf(lrelu(((const float*)&g_as1[sc])[h] + add));
        float4 hv = *(const float4*)&g_h1[sc * 128 + co];
        s += w;
        acc.x = fmaf(w, hv.x, acc.x); acc.y = fmaf(w, hv.y, acc.y);
        acc.z = fmaf(w, hv.z, acc.z); acc.w = fmaf(w, hv.w, acc.w);
    }
    float inv = 1.0f / (s + 1e-16f);
    float4 bv = *(const float4*)&b1[co];
    float4 o;
    o.x = acc.x * inv + bv.x;
    o.y = acc.y * inv + bv.y;
    o.z = acc.z * inv + bv.z;
    o.w = acc.w * inv + bv.w;
    o.x = o.x > 0.0f ? o.x : expm1f(o.x);
    o.y = o.y > 0.0f ? o.y : expm1f(o.y);
    o.z = o.z > 0.0f ? o.z : expm1f(o.z);
    o.w = o.w > 0.0f ? o.w : expm1f(o.w);
    *(float4*)&g_h1e[d * 128 + co] = o;
}

// ---------------- gemm2 (FFMA2, 16 nodes/block, 64 threads) -------------------
__global__ void __launch_bounds__(64) gemm2_kernel(
        const float* __restrict__ W,
        const float* __restrict__ as, const float* __restrict__ ad) {
    __shared__ float xs[16][128];
    __shared__ float ps[16][2], pd[16][2];
    int n0 = blockIdx.x * 16;
    int t = threadIdx.x;
    const float4* x4 = (const float4*)(g_h1e + n0 * 128);
    float4* xs4 = (float4*)xs;
#pragma unroll
    for (int r = 0; r < 8; r++) xs4[t + r * 64] = x4[t + r * 64];
    __syncthreads();
    int j = t;
    unsigned long long acc2[16];
#pragma unroll
    for (int n = 0; n < 16; n++) acc2[n] = 0ull;
#pragma unroll
    for (int k = 0; k < 128; k += 4) {
        float w0 = W[(k + 0) * 64 + j];
        float w1 = W[(k + 1) * 64 + j];
        float w2 = W[(k + 2) * 64 + j];
        float w3 = W[(k + 3) * 64 + j];
        unsigned long long wp01 = pack2(w0, w1);
        unsigned long long wp23 = pack2(w2, w3);
#pragma unroll
        for (int n = 0; n < 16; n++) {
            float4 xv = *(const float4*)&xs[n][k];
            unsigned long long x01 = pack2(xv.x, xv.y);
            unsigned long long x23 = pack2(xv.z, xv.w);
            acc2[n] = fma2(x01, wp01, acc2[n]);
            acc2[n] = fma2(x23, wp23, acc2[n]);
        }
    }
    float asj = as[j], adj = ad[j];
    int w = t >> 5;
#pragma unroll
    for (int n = 0; n < 16; n++) {
        float a = sum2(acc2[n]);
        g_h2[(n0 + n) * 64 + j] = a;
        float vs = a * asj;
        float vd = a * adj;
#pragma unroll
        for (int o = 16; o; o >>= 1) {
            vs += __shfl_xor_sync(0xffffffffu, vs, o);
            vd += __shfl_xor_sync(0xffffffffu, vd, o);
        }
        if ((t & 31) == 0) { ps[n][w] = vs; pd[n][w] = vd; }
    }
    __syncthreads();
    if (t < 16) {
        g_as2[n0 + t] = ps[t][0] + ps[t][1];
        g_ad2[n0 + t] = pd[t][0] + pd[t][1];
    }
}

// ---------------- fused softmax aggregation (max-free), layer 2 --------------
__global__ void __launch_bounds__(256) agg2_kernel(
        float* __restrict__ out, const float* __restrict__ b2) {
    int warp = threadIdx.x >> 5, lane = threadIdx.x & 31;
    int d = blockIdx.x * 8 + warp;
    int lo = g_row[d], hi = g_row[d + 1];
    float add = g_ad2[d];
    float s = 0.0f;
    float2 acc = make_float2(0, 0);
    int co = lane * 2;
    int i = lo;
    for (; i + 4 <= hi; i += 4) {
        int s0 = g_csrc[i], s1 = g_csrc[i + 1], s2 = g_csrc[i + 2], s3 = g_csrc[i + 3];
        float a0 = g_as2[s0], a1 = g_as2[s1], a2 = g_as2[s2], a3 = g_as2[s3];
        float2 h0 = *(const float2*)&g_h2[s0 * 64 + co];
        float2 h1 = *(const float2*)&g_h2[s1 * 64 + co];
        float2 h2 = *(const float2*)&g_h2[s2 * 64 + co];
        float2 h3 = *(const float2*)&g_h2[s3 * 64 + co];
        float w0 = __expf(lrelu(a0 + add));
        float w1 = __expf(lrelu(a1 + add));
        float w2 = __expf(lrelu(a2 + add));
        float w3 = __expf(lrelu(a3 + add));
        s += (w0 + w1) + (w2 + w3);
        acc.x = fmaf(w0, h0.x, acc.x); acc.y = fmaf(w0, h0.y, acc.y);
        acc.x = fmaf(w1, h1.x, acc.x); acc.y = fmaf(w1, h1.y, acc.y);
        acc.x = fmaf(w2, h2.x, acc.x); acc.y = fmaf(w2, h2.y, acc.y);
        acc.x = fmaf(w3, h3.x, acc.x); acc.y = fmaf(w3, h3.y, acc.y);
    }
    for (; i < hi; i++) {
        int sc = g_csrc[i];
        float w = __expf(lrelu(g_as2[sc] + add));
        float2 hv = *(const float2*)&g_h2[sc * 64 + co];
        s += w;
        acc.x = fmaf(w, hv.x, acc.x);
        acc.y = fmaf(w, hv.y, acc.y);
    }
    float inv = 1.0f / (s + 1e-16f);
    float2 o;
    o.x = acc.x * inv + b2[co];
    o.y = acc.y * inv + b2[co + 1];
    *(float2*)&out[d * 64 + co] = o;
}

// ---------------- launch -------------------------------------------------------
extern "C" void kernel_launch(void* const* d_in, const int* in_sizes, int n_in,
                              void* d_out, int out_size) {
    const float* x   = (const float*)d_in[0];
    const void*  ei  = d_in[1];
    const float* W1  = (const float*)d_in[2];
    const float* as1 = (const float*)d_in[3];
    const float* ad1 = (const float*)d_in[4];
    const float* b1  = (const float*)d_in[5];
    const float* W2  = (const float*)d_in[6];
    const float* as2 = (const float*)d_in[7];
    const float* ad2 = (const float*)d_in[8];
    const float* b2  = (const float*)d_in[9];
    float*       out = (float*)d_out;

    const int TB = 256;
    auto nb = [](long long n, int tb) { return (int)((n + tb - 1) / tb); };

    zero_detect_kernel<<<SCAN_B, 256>>>(ei);
    convert_hist_kernel<<<nb(ET, TB), TB>>>(ei);
    scan1_kernel<<<SCAN_B, 256>>>();
    scan3_kernel<<<SCAN_B, 256>>>();
    scatter_kernel<<<nb(ET, TB), TB>>>();

    gemm1_kernel<<<NN / 16, 128>>>(x, W1, as1, ad1);
    agg1_kernel<<<NN / 8, 256>>>(b1);

    gemm2_kernel<<<NN / 16, 64>>>(W2, as2, ad2);
    agg2_kernel<<<NN / 8, 256>>>(out, b2);
}

// round 9
// speedup vs baseline: 1.2495x; 1.0886x over previous
#include <cuda_runtime.h>
#include <cuda_bf16.h>
#include <math.h>

#define NN 50000
#define EE 800000
#define ET (EE + NN)
#define F1 128
#define C2 64
#define NEG 0.2f

#define SCAN_B 196                       // ceil(50000/256)

// ---------------- scratch ----------------------------------------------------
__device__ int    g_is64;
__device__ int    g_src [ET];
__device__ int    g_dst [ET];
__device__ int    g_row [NN + 1];
__device__ int    g_wpos[NN];
__device__ int    g_bsum[SCAN_B];
__device__ int    g_csrc[ET];

__device__ float  g_h1  [NN * F1];
__device__ float  g_h1e [NN * F1];
__device__ float4 g_as1 [NN];
__device__ float4 g_ad1 [NN];

__device__ float  g_h2  [NN * C2];
__device__ float  g_as2 [NN];
__device__ float  g_ad2 [NN];

__device__ __forceinline__ float lrelu(float v) { return v > 0.0f ? v : NEG * v; }

// ---------------- packed f32x2 helpers ----------------------------------------
__device__ __forceinline__ unsigned long long fma2(unsigned long long a,
                                                   unsigned long long b,
                                                   unsigned long long c) {
    unsigned long long d;
    asm("fma.rn.f32x2 %0, %1, %2, %3;" : "=l"(d) : "l"(a), "l"(b), "l"(c));
    return d;
}
__device__ __forceinline__ unsigned long long pack2(float lo, float hi) {
    unsigned long long r;
    asm("mov.b64 %0, {%1, %2};" : "=l"(r) : "f"(lo), "f"(hi));
    return r;
}
__device__ __forceinline__ float sum2(unsigned long long v) {
    float lo, hi;
    asm("mov.b64 {%0, %1}, %2;" : "=f"(lo), "=f"(hi) : "l"(v));
    return lo + hi;
}

// ---------------- zero counters + dtype detect ---------------------------------
__global__ void zero_detect_kernel(const void* __restrict__ ei) {
    int i = blockIdx.x * blockDim.x + threadIdx.x;
    if (i < NN) g_wpos[i] = 0;
    if (blockIdx.x == 0) {
        const unsigned long long* p = (const unsigned long long*)ei;
        int bad = (p[threadIdx.x] >= (unsigned long long)NN) ? 1 : 0;
        int anybad = __syncthreads_or(bad);
        if (threadIdx.x == 0) g_is64 = anybad ? 0 : 1;
    }
}

__global__ void convert_hist_kernel(const void* __restrict__ ei) {
    int e = blockIdx.x * blockDim.x + threadIdx.x;
    if (e >= ET) return;
    int s, d;
    if (e >= EE) s = d = e - EE;
    else if (g_is64) {
        s = (int)((const long long*)ei)[e];
        d = (int)((const long long*)ei)[EE + e];
    } else {
        s = ((const int*)ei)[e];
        d = ((const int*)ei)[EE + e];
    }
    g_src[e] = s;
    g_dst[e] = d;
    atomicAdd(&g_wpos[d], 1);
}

// ---------------- scan ----------------------------------------------------------
__device__ __forceinline__ int block_excl_scan(int v, int t, int* total) {
    __shared__ int wsum[8];
    int lane = t & 31, w = t >> 5;
    int inc = v;
#pragma unroll
    for (int o = 1; o < 32; o <<= 1) {
        int u = __shfl_up_sync(0xffffffffu, inc, o);
        if (lane >= o) inc += u;
    }
    if (lane == 31) wsum[w] = inc;
    __syncthreads();
    if (w == 0) {
        int ws = (lane < 8) ? wsum[lane] : 0;
#pragma unroll
        for (int o = 1; o < 8; o <<= 1) {
            int u = __shfl_up_sync(0xffffffffu, ws, o);
            if (lane >= o) ws += u;
        }
        if (lane < 8) wsum[lane] = ws;
    }
    __syncthreads();
    int base = (w > 0) ? wsum[w - 1] : 0;
    *total = wsum[7];
    return base + inc - v;
}

__global__ void scan1_kernel() {
    int t = threadIdx.x;
    int i = blockIdx.x * 256 + t;
    int v = (i < NN) ? g_wpos[i] : 0;
    int total;
    int ex = block_excl_scan(v, t, &total);
    if (i < NN) g_row[i] = ex;
    if (t == 0) g_bsum[blockIdx.x] = total;
}

__global__ void scan3_kernel() {
    __shared__ int ws[8];
    __shared__ int sbase;
    int t = threadIdx.x, b = blockIdx.x;
    int lane = t & 31, w = t >> 5;
    int v = (t < SCAN_B && t < b) ? g_bsum[t] : 0;
#pragma unroll
    for (int o = 16; o; o >>= 1) v += __shfl_xor_sync(0xffffffffu, v, o);
    if (lane == 0) ws[w] = v;
    __syncthreads();
    if (t == 0) {
        int tot = 0;
#pragma unroll
        for (int k = 0; k < 8; k++) tot += ws[k];
        sbase = tot;
    }
    __syncthreads();
    int i = b * 256 + t;
    if (i < NN) {
        int r = g_row[i] + sbase;
        g_row[i] = r;
        g_wpos[i] = r;
    }
    if (i == 0) g_row[NN] = ET;
}

__global__ void scatter_kernel() {
    int e = blockIdx.x * blockDim.x + threadIdx.x;
    if (e >= ET) return;
    int d = g_dst[e];
    int p = atomicAdd(&g_wpos[d], 1);
    g_csrc[p] = g_src[e];
}

// ---------------- gemm1 (FFMA2, LDS.128 loads, 16 nodes/block) ----------------
__global__ void __launch_bounds__(128) gemm1_kernel(
        const float* __restrict__ x, const float* __restrict__ W,
        const float* __restrict__ as, const float* __restrict__ ad) {
    __shared__ float xs[16][128];
    int n0 = blockIdx.x * 16;
    int t = threadIdx.x;
    const float4* x4 = (const float4*)(x + n0 * 128);
    float4* xs4 = (float4*)xs;
#pragma unroll
    for (int r = 0; r < 4; r++) xs4[t + r * 128] = x4[t + r * 128];
    __syncthreads();
    int j = t;
    unsigned long long acc2[16];
#pragma unroll
    for (int n = 0; n < 16; n++) acc2[n] = 0ull;
#pragma unroll
    for (int k = 0; k < 128; k += 4) {
        float w0 = W[(k + 0) * 128 + j];
        float w1 = W[(k + 1) * 128 + j];
        float w2 = W[(k + 2) * 128 + j];
        float w3 = W[(k + 3) * 128 + j];
        unsigned long long wp01 = pack2(w0, w1);
        unsigned long long wp23 = pack2(w2, w3);
#pragma unroll
        for (int n = 0; n < 16; n++) {
            float4 xv = *(const float4*)&xs[n][k];
            unsigned long long x01 = pack2(xv.x, xv.y);
            unsigned long long x23 = pack2(xv.z, xv.w);
            acc2[n] = fma2(x01, wp01, acc2[n]);
            acc2[n] = fma2(x23, wp23, acc2[n]);
        }
    }
    float asj = as[j], adj = ad[j];
    int h = j >> 5;
#pragma unroll
    for (int n = 0; n < 16; n++) {
        float a = sum2(acc2[n]);
        g_h1[(n0 + n) * 128 + j] = a;
        float vs = a * asj;
        float vd = a * adj;
#pragma unroll
        for (int o = 16; o; o >>= 1) {
            vs += __shfl_xor_sync(0xffffffffu, vs, o);
            vd += __shfl_xor_sync(0xffffffffu, vd, o);
        }
        if ((j & 31) == 0) {
            ((float*)&g_as1[n0 + n])[h] = vs;
            ((float*)&g_ad1[n0 + n])[h] = vd;
        }
    }
}

// ---------------- fused softmax aggregation (max-free), layer 1 --------------
__global__ void __launch_bounds__(256) agg1_kernel(const float* __restrict__ b1) {
    int warp = threadIdx.x >> 5, lane = threadIdx.x & 31;
    int d = blockIdx.x * 8 + warp;
    int lo = g_row[d], hi = g_row[d + 1];
    int h = lane >> 3;
    float add = ((const float*)&g_ad1[d])[h];
    float s = 0.0f;
    float4 acc = make_float4(0, 0, 0, 0);
    int co = lane * 4;
    int i = lo;
    for (; i + 4 <= hi; i += 4) {
        int s0 = g_csrc[i], s1 = g_csrc[i + 1], s2 = g_csrc[i + 2], s3 = g_csrc[i + 3];
        float a0 = ((const float*)&g_as1[s0])[h];
        float a1 = ((const float*)&g_as1[s1])[h];
        float a2 = ((const float*)&g_as1[s2])[h];
        float a3 = ((const float*)&g_as1[s3])[h];
        float4 h0 = *(const float4*)&g_h1[s0 * 128 + co];
        float4 h1 = *(const float4*)&g_h1[s1 * 128 + co];
        float4 h2 = *(const float4*)&g_h1[s2 * 128 + co];
        float4 h3 = *(const float4*)&g_h1[s3 * 128 + co];
        float w0 = __expf(lrelu(a0 + add));
        float w1 = __expf(lrelu(a1 + add));
        float w2 = __expf(lrelu(a2 + add));
        float w3 = __expf(lrelu(a3 + add));
        s += (w0 + w1) + (w2 + w3);
        acc.x = fmaf(w0, h0.x, acc.x); acc.y = fmaf(w0, h0.y, acc.y);
        acc.z = fmaf(w0, h0.z, acc.z); acc.w = fmaf(w0, h0.w, acc.w);
        acc.x = fmaf(w1, h1.x, acc.x); acc.y = fmaf(w1, h1.y, acc.y);
        acc.z = fmaf(w1, h1.z, acc.z); acc.w = fmaf(w1, h1.w, acc.w);
        acc.x = fmaf(w2, h2.x, acc.x); acc.y = fmaf(w2, h2.y, acc.y);
        acc.z = fmaf(w2, h2.z, acc.z); acc.w = fmaf(w2, h2.w, acc.w);
        acc.x = fmaf(w3, h3.x, acc.x); acc.y = fmaf(w3, h3.y, acc.y);
        acc.z = fmaf(w3, h3.z, acc.z); acc.w = fmaf(w3, h3.w, acc.w);
    }
    for (; i < hi; i++) {
        int sc = g_csrc[i];
        float w = __expf(lrelu(((const float*)&g_as1[sc])[h] + add));
        float4 hv = *(const float4*)&g_h1[sc * 128 + co];
        s += w;
        acc.x = fmaf(w, hv.x, acc.x); acc.y = fmaf(w, hv.y, acc.y);
        acc.z = fmaf(w, hv.z, acc.z); acc.w = fmaf(w, hv.w, acc.w);
    }
    float inv = 1.0f / (s + 1e-16f);
    float4 bv = *(const float4*)&b1[co];
    float4 o;
    o.x = acc.x * inv + bv.x;
    o.y = acc.y * inv + bv.y;
    o.z = acc.z * inv + bv.z;
    o.w = acc.w * inv + bv.w;
    o.x = o.x > 0.0f ? o.x : expm1f(o.x);
    o.y = o.y > 0.0f ? o.y : expm1f(o.y);
    o.z = o.z > 0.0f ? o.z : expm1f(o.z);
    o.w = o.w > 0.0f ? o.w : expm1f(o.w);
    *(float4*)&g_h1e[d * 128 + co] = o;
}

// ---------------- gemm2 (FFMA2, 16 nodes/block, 64 threads) -------------------
__global__ void __launch_bounds__(64) gemm2_kernel(
        const float* __restrict__ W,
        const float* __restrict__ as, const float* __restrict__ ad) {
    __shared__ float xs[16][128];
    __shared__ float ps[16][2], pd[16][2];
    int n0 = blockIdx.x * 16;
    int t = threadIdx.x;
    const float4* x4 = (const float4*)(g_h1e + n0 * 128);
    float4* xs4 = (float4*)xs;
#pragma unroll
    for (int r = 0; r < 8; r++) xs4[t + r * 64] = x4[t + r * 64];
    __syncthreads();
    int j = t;
    unsigned long long acc2[16];
#pragma unroll
    for (int n = 0; n < 16; n++) acc2[n] = 0ull;
#pragma unroll
    for (int k = 0; k < 128; k += 4) {
        float w0 = W[(k + 0) * 64 + j];
        float w1 = W[(k + 1) * 64 + j];
        float w2 = W[(k + 2) * 64 + j];
        float w3 = W[(k + 3) * 64 + j];
        unsigned long long wp01 = pack2(w0, w1);
        unsigned long long wp23 = pack2(w2, w3);
#pragma unroll
        for (int n = 0; n < 16; n++) {
            float4 xv = *(const float4*)&xs[n][k];
            unsigned long long x01 = pack2(xv.x, xv.y);
            unsigned long long x23 = pack2(xv.z, xv.w);
            acc2[n] = fma2(x01, wp01, acc2[n]);
            acc2[n] = fma2(x23, wp23, acc2[n]);
        }
    }
    float asj = as[j], adj = ad[j];
    int w = t >> 5;
#pragma unroll
    for (int n = 0; n < 16; n++) {
        float a = sum2(acc2[n]);
        g_h2[(n0 + n) * 64 + j] = a;
        float vs = a * asj;
        float vd = a * adj;
#pragma unroll
        for (int o = 16; o; o >>= 1) {
            vs += __shfl_xor_sync(0xffffffffu, vs, o);
            vd += __shfl_xor_sync(0xffffffffu, vd, o);
        }
        if ((t & 31) == 0) { ps[n][w] = vs; pd[n][w] = vd; }
    }
    __syncthreads();
    if (t < 16) {
        g_as2[n0 + t] = ps[t][0] + ps[t][1];
        g_ad2[n0 + t] = pd[t][0] + pd[t][1];
    }
}

// ---------------- fused softmax aggregation (max-free), layer 2 --------------
__global__ void __launch_bounds__(256) agg2_kernel(
        float* __restrict__ out, const float* __restrict__ b2) {
    int warp = threadIdx.x >> 5, lane = threadIdx.x & 31;
    int d = blockIdx.x * 8 + warp;
    int lo = g_row[d], hi = g_row[d + 1];
    float add = g_ad2[d];
    float s = 0.0f;
    float2 acc = make_float2(0, 0);
    int co = lane * 2;
    int i = lo;
    for (; i + 4 <= hi; i += 4) {
        int s0 = g_csrc[i], s1 = g_csrc[i + 1], s2 = g_csrc[i + 2], s3 = g_csrc[i + 3];
        float a0 = g_as2[s0], a1 = g_as2[s1], a2 = g_as2[s2], a3 = g_as2[s3];
        float2 h0 = *(const float2*)&g_h2[s0 * 64 + co];
        float2 h1 = *(const float2*)&g_h2[s1 * 64 + co];
        float2 h2 = *(const float2*)&g_h2[s2 * 64 + co];
        float2 h3 = *(const float2*)&g_h2[s3 * 64 + co];
        float w0 = __expf(lrelu(a0 + add));
        float w1 = __expf(lrelu(a1 + add));
        float w2 = __expf(lrelu(a2 + add));
        float w3 = __expf(lrelu(a3 + add));
        s += (w0 + w1) + (w2 + w3);
        acc.x = fmaf(w0, h0.x, acc.x); acc.y = fmaf(w0, h0.y, acc.y);
        acc.x = fmaf(w1, h1.x, acc.x); acc.y = fmaf(w1, h1.y, acc.y);
        acc.x = fmaf(w2, h2.x, acc.x); acc.y = fmaf(w2, h2.y, acc.y);
        acc.x = fmaf(w3, h3.x, acc.x); acc.y = fmaf(w3, h3.y, acc.y);
    }
    for (; i < hi; i++) {
        int sc = g_csrc[i];
        float w = __expf(lrelu(g_as2[sc] + add));
        float2 hv = *(const float2*)&g_h2[sc * 64 + co];
        s += w;
        acc.x = fmaf(w, hv.x, acc.x);
        acc.y = fmaf(w, hv.y, acc.y);
    }
    float inv = 1.0f / (s + 1e-16f);
    float2 o;
    o.x = acc.x * inv + b2[co];
    o.y = acc.y * inv + b2[co + 1];
    *(float2*)&out[d * 64 + co] = o;
}

// ---------------- launch -------------------------------------------------------
extern "C" void kernel_launch(void* const* d_in, const int* in_sizes, int n_in,
                              void* d_out, int out_size) {
    const float* x   = (const float*)d_in[0];
    const void*  ei  = d_in[1];
    const float* W1  = (const float*)d_in[2];
    const float* as1 = (const float*)d_in[3];
    const float* ad1 = (const float*)d_in[4];
    const float* b1  = (const float*)d_in[5];
    const float* W2  = (const float*)d_in[6];
    const float* as2 = (const float*)d_in[7];
    const float* ad2 = (const float*)d_in[8];
    const float* b2  = (const float*)d_in[9];
    float*       out = (float*)d_out;

    const int TB = 256;
    auto nb = [](long long n, int tb) { return (int)((n + tb - 1) / tb); };

    // fork: gemm1 (x/W1 only) runs concurrently with the CSR build chain
    cudaStream_t s2;
    cudaStreamCreateWithFlags(&s2, cudaStreamNonBlocking);
    cudaEvent_t e1, e2;
    cudaEventCreateWithFlags(&e1, cudaEventDisableTiming);
    cudaEventCreateWithFlags(&e2, cudaEventDisableTiming);

    cudaEventRecord(e1, 0);
    cudaStreamWaitEvent(s2, e1, 0);
    gemm1_kernel<<<NN / 16, 128, 0, s2>>>(x, W1, as1, ad1);
    cudaEventRecord(e2, s2);

    zero_detect_kernel<<<SCAN_B, 256>>>(ei);
    convert_hist_kernel<<<nb(ET, TB), TB>>>(ei);
    scan1_kernel<<<SCAN_B, 256>>>();
    scan3_kernel<<<SCAN_B, 256>>>();
    scatter_kernel<<<nb(ET, TB), TB>>>();

    cudaStreamWaitEvent(0, e2, 0);
    agg1_kernel<<<NN / 8, 256>>>(b1);
    gemm2_kernel<<<NN / 16, 64>>>(W2, as2, ad2);
    agg2_kernel<<<NN / 8, 256>>>(out, b2);

    cudaEventDestroy(e1);
    cudaEventDestroy(e2);
    cudaStreamDestroy(s2);
}

// round 11
// speedup vs baseline: 1.2665x; 1.0135x over previous
#include <cuda_runtime.h>
#include <cuda_fp16.h>
#include <math.h>

#define NN 50000
#define EE 800000
#define ET (EE + NN)
#define F1 128
#define C2 64
#define NEG 0.2f

#define SCAN_B 196                       // ceil(50000/256)

// ---------------- scratch ----------------------------------------------------
__device__ int    g_is64;
__device__ int    g_src [ET];
__device__ int    g_dst [ET];
__device__ int    g_row [NN + 1];
__device__ int    g_wpos[NN];
__device__ int    g_bsum[SCAN_B];
__device__ int    g_csrc[ET];

__device__ __half g_h1h[NN * F1];          // layer1 features (fp16 for gather BW)
__device__ float  g_h1e [NN * F1];         // elu output (fp32, read densely by gemm2)
__device__ float4 g_as1 [NN];
__device__ float4 g_ad1 [NN];

__device__ __half g_h2h[NN * C2];          // layer2 features (fp16)
__device__ float  g_as2 [NN];
__device__ float  g_ad2 [NN];

__device__ __forceinline__ float lrelu(float v) { return v > 0.0f ? v : NEG * v; }

// ---------------- packed f32x2 helpers ----------------------------------------
__device__ __forceinline__ unsigned long long fma2(unsigned long long a,
                                                   unsigned long long b,
                                                   unsigned long long c) {
    unsigned long long d;
    asm("fma.rn.f32x2 %0, %1, %2, %3;" : "=l"(d) : "l"(a), "l"(b), "l"(c));
    return d;
}
__device__ __forceinline__ unsigned long long pack2(float lo, float hi) {
    unsigned long long r;
    asm("mov.b64 %0, {%1, %2};" : "=l"(r) : "f"(lo), "f"(hi));
    return r;
}
__device__ __forceinline__ float sum2(unsigned long long v) {
    float lo, hi;
    asm("mov.b64 {%0, %1}, %2;" : "=f"(lo), "=f"(hi) : "l"(v));
    return lo + hi;
}

// ---------------- zero counters + dtype detect ---------------------------------
__global__ void zero_detect_kernel(const void* __restrict__ ei) {
    int i = blockIdx.x * blockDim.x + threadIdx.x;
    if (i < NN) g_wpos[i] = 0;
    if (blockIdx.x == 0) {
        const unsigned long long* p = (const unsigned long long*)ei;
        int bad = (p[threadIdx.x] >= (unsigned long long)NN) ? 1 : 0;
        int anybad = __syncthreads_or(bad);
        if (threadIdx.x == 0) g_is64 = anybad ? 0 : 1;
    }
}

__global__ void convert_hist_kernel(const void* __restrict__ ei) {
    int e = blockIdx.x * blockDim.x + threadIdx.x;
    if (e >= ET) return;
    int s, d;
    if (e >= EE) s = d = e - EE;
    else if (g_is64) {
        s = (int)((const long long*)ei)[e];
        d = (int)((const long long*)ei)[EE + e];
    } else {
        s = ((const int*)ei)[e];
        d = ((const int*)ei)[EE + e];
    }
    g_src[e] = s;
    g_dst[e] = d;
    atomicAdd(&g_wpos[d], 1);
}

// ---------------- scan ----------------------------------------------------------
__device__ __forceinline__ int block_excl_scan(int v, int t, int* total) {
    __shared__ int wsum[8];
    int lane = t & 31, w = t >> 5;
    int inc = v;
#pragma unroll
    for (int o = 1; o < 32; o <<= 1) {
        int u = __shfl_up_sync(0xffffffffu, inc, o);
        if (lane >= o) inc += u;
    }
    if (lane == 31) wsum[w] = inc;
    __syncthreads();
    if (w == 0) {
        int ws = (lane < 8) ? wsum[lane] : 0;
#pragma unroll
        for (int o = 1; o < 8; o <<= 1) {
            int u = __shfl_up_sync(0xffffffffu, ws, o);
            if (lane >= o) ws += u;
        }
        if (lane < 8) wsum[lane] = ws;
    }
    __syncthreads();
    int base = (w > 0) ? wsum[w - 1] : 0;
    *total = wsum[7];
    return base + inc - v;
}

__global__ void scan1_kernel() {
    int t = threadIdx.x;
    int i = blockIdx.x * 256 + t;
    int v = (i < NN) ? g_wpos[i] : 0;
    int total;
    int ex = block_excl_scan(v, t, &total);
    if (i < NN) g_row[i] = ex;
    if (t == 0) g_bsum[blockIdx.x] = total;
}

__global__ void scan3_kernel() {
    __shared__ int ws[8];
    __shared__ int sbase;
    int t = threadIdx.x, b = blockIdx.x;
    int lane = t & 31, w = t >> 5;
    int v = (t < SCAN_B && t < b) ? g_bsum[t] : 0;
#pragma unroll
    for (int o = 16; o; o >>= 1) v += __shfl_xor_sync(0xffffffffu, v, o);
    if (lane == 0) ws[w] = v;
    __syncthreads();
    if (t == 0) {
        int tot = 0;
#pragma unroll
        for (int k = 0; k < 8; k++) tot += ws[k];
        sbase = tot;
    }
    __syncthreads();
    int i = b * 256 + t;
    if (i < NN) {
        int r = g_row[i] + sbase;
        g_row[i] = r;
        g_wpos[i] = r;
    }
    if (i == 0) g_row[NN] = ET;
}

__global__ void scatter_kernel() {
    int e = blockIdx.x * blockDim.x + threadIdx.x;
    if (e >= ET) return;
    int d = g_dst[e];
    int p = atomicAdd(&g_wpos[d], 1);
    g_csrc[p] = g_src[e];
}

// ---------------- gemm1 (FFMA2, 16 nodes/block, fp16 h1 out) -------------------
__global__ void __launch_bounds__(128) gemm1_kernel(
        const float* __restrict__ x, const float* __restrict__ W,
        const float* __restrict__ as, const float* __restrict__ ad) {
    __shared__ float xs[16][128];
    int n0 = blockIdx.x * 16;
    int t = threadIdx.x;
    const float4* x4 = (const float4*)(x + n0 * 128);
    float4* xs4 = (float4*)xs;
#pragma unroll
    for (int r = 0; r < 4; r++) xs4[t + r * 128] = x4[t + r * 128];
    __syncthreads();
    int j = t;
    unsigned long long acc2[16];
#pragma unroll
    for (int n = 0; n < 16; n++) acc2[n] = 0ull;
#pragma unroll
    for (int k = 0; k < 128; k += 4) {
        float w0 = W[(k + 0) * 128 + j];
        float w1 = W[(k + 1) * 128 + j];
        float w2 = W[(k + 2) * 128 + j];
        float w3 = W[(k + 3) * 128 + j];
        unsigned long long wp01 = pack2(w0, w1);
        unsigned long long wp23 = pack2(w2, w3);
#pragma unroll
        for (int n = 0; n < 16; n++) {
            float4 xv = *(const float4*)&xs[n][k];
            unsigned long long x01 = pack2(xv.x, xv.y);
            unsigned long long x23 = pack2(xv.z, xv.w);
            acc2[n] = fma2(x01, wp01, acc2[n]);
            acc2[n] = fma2(x23, wp23, acc2[n]);
        }
    }
    float asj = as[j], adj = ad[j];
    int h = j >> 5;
#pragma unroll
    for (int n = 0; n < 16; n++) {
        float a = sum2(acc2[n]);
        g_h1h[(n0 + n) * 128 + j] = __float2half(a);
        float vs = a * asj;
        float vd = a * adj;
#pragma unroll
        for (int o = 16; o; o >>= 1) {
            vs += __shfl_xor_sync(0xffffffffu, vs, o);
            vd += __shfl_xor_sync(0xffffffffu, vd, o);
        }
        if ((j & 31) == 0) {
            ((float*)&g_as1[n0 + n])[h] = vs;
            ((float*)&g_ad1[n0 + n])[h] = vd;
        }
    }
}

// ---------------- fused softmax aggregation (max-free, fp16 gather), layer 1 --
__device__ __forceinline__ float4 h16x4_to_f4(uint2 raw) {
    __half2 p0 = *(__half2*)&raw.x;
    __half2 p1 = *(__half2*)&raw.y;
    float2 f0 = __half22float2(p0);
    float2 f1 = __half22float2(p1);
    return make_float4(f0.x, f0.y, f1.x, f1.y);
}

__global__ void __launch_bounds__(256) agg1_kernel(const float* __restrict__ b1) {
    int warp = threadIdx.x >> 5, lane = threadIdx.x & 31;
    int d = blockIdx.x * 8 + warp;
    int lo = g_row[d], hi = g_row[d + 1];
    int h = lane >> 3;
    float add = ((const float*)&g_ad1[d])[h];
    float s = 0.0f;
    float4 acc = make_float4(0, 0, 0, 0);
    int co = lane * 4;
    int i = lo;
    for (; i + 4 <= hi; i += 4) {
        int s0 = g_csrc[i], s1 = g_csrc[i + 1], s2 = g_csrc[i + 2], s3 = g_csrc[i + 3];
        float a0 = ((const float*)&g_as1[s0])[h];
        float a1 = ((const float*)&g_as1[s1])[h];
        float a2 = ((const float*)&g_as1[s2])[h];
        float a3 = ((const float*)&g_as1[s3])[h];
        uint2 r0 = *(const uint2*)&g_h1h[s0 * 128 + co];
        uint2 r1 = *(const uint2*)&g_h1h[s1 * 128 + co];
        uint2 r2 = *(const uint2*)&g_h1h[s2 * 128 + co];
        uint2 r3 = *(const uint2*)&g_h1h[s3 * 128 + co];
        float w0 = __expf(lrelu(a0 + add));
        float w1 = __expf(lrelu(a1 + add));
        float w2 = __expf(lrelu(a2 + add));
        float w3 = __expf(lrelu(a3 + add));
        float4 h0 = h16x4_to_f4(r0);
        float4 h1 = h16x4_to_f4(r1);
        float4 h2 = h16x4_to_f4(r2);
        float4 h3 = h16x4_to_f4(r3);
        s += (w0 + w1) + (w2 + w3);
        acc.x = fmaf(w0, h0.x, acc.x); acc.y = fmaf(w0, h0.y, acc.y);
        acc.z = fmaf(w0, h0.z, acc.z); acc.w = fmaf(w0, h0.w, acc.w);
        acc.x = fmaf(w1, h1.x, acc.x); acc.y = fmaf(w1, h1.y, acc.y);
        acc.z = fmaf(w1, h1.z, acc.z); acc.w = fmaf(w1, h1.w, acc.w);
        acc.x = fmaf(w2, h2.x, acc.x); acc.y = fmaf(w2, h2.y, acc.y);
        acc.z = fmaf(w2, h2.z, acc.z); acc.w = fmaf(w2, h2.w, acc.w);
        acc.x = fmaf(w3, h3.x, acc.x); acc.y = fmaf(w3, h3.y, acc.y);
        acc.z = fmaf(w3, h3.z, acc.z); acc.w = fmaf(w3, h3.w, acc.w);
    }
    for (; i < hi; i++) {
        int sc = g_csrc[i];
        float w = __expf(lrelu(((const float*)&g_as1[sc])[h] + add));
        float4 hv = h16x4_to_f4(*(const uint2*)&g_h1h[sc * 128 + co]);
        s += w;
        acc.x = fmaf(w, hv.x, acc.x); acc.y = fmaf(w, hv.y, acc.y);
        acc.z = fmaf(w, hv.z, acc.z); acc.w = fmaf(w, hv.w, acc.w);
    }
    float inv = 1.0f / (s + 1e-16f);
    float4 bv = *(const float4*)&b1[co];
    float4 o;
    o.x = acc.x * inv + bv.x;
    o.y = acc.y * inv + bv.y;
    o.z = acc.z * inv + bv.z;
    o.w = acc.w * inv + bv.w;
    o.x = o.x > 0.0f ? o.x : expm1f(o.x);
    o.y = o.y > 0.0f ? o.y : expm1f(o.y);
    o.z = o.z > 0.0f ? o.z : expm1f(o.z);
    o.w = o.w > 0.0f ? o.w : expm1f(o.w);
    *(float4*)&g_h1e[d * 128 + co] = o;
}

// ---------------- gemm2 (FFMA2, 16 nodes/block, fp16 h2 out) -------------------
__global__ void __launch_bounds__(64) gemm2_kernel(
        const float* __restrict__ W,
        const float* __restrict__ as, const float* __restrict__ ad) {
    __shared__ float xs[16][128];
    __shared__ float ps[16][2], pd[16][2];
    int n0 = blockIdx.x * 16;
    int t = threadIdx.x;
    const float4* x4 = (const float4*)(g_h1e + n0 * 128);
    float4* xs4 = (float4*)xs;
#pragma unroll
    for (int r = 0; r < 8; r++) xs4[t + r * 64] = x4[t + r * 64];
    __syncthreads();
    int j = t;
    unsigned long long acc2[16];
#pragma unroll
    for (int n = 0; n < 16; n++) acc2[n] = 0ull;
#pragma unroll
    for (int k = 0; k < 128; k += 4) {
        float w0 = W[(k + 0) * 64 + j];
        float w1 = W[(k + 1) * 64 + j];
        float w2 = W[(k + 2) * 64 + j];
        float w3 = W[(k + 3) * 64 + j];
        unsigned long long wp01 = pack2(w0, w1);
        unsigned long long wp23 = pack2(w2, w3);
#pragma unroll
        for (int n = 0; n < 16; n++) {
            float4 xv = *(const float4*)&xs[n][k];
            unsigned long long x01 = pack2(xv.x, xv.y);
            unsigned long long x23 = pack2(xv.z, xv.w);
            acc2[n] = fma2(x01, wp01, acc2[n]);
            acc2[n] = fma2(x23, wp23, acc2[n]);
        }
    }
    float asj = as[j], adj = ad[j];
    int w = t >> 5;
#pragma unroll
    for (int n = 0; n < 16; n++) {
        float a = sum2(acc2[n]);
        g_h2h[(n0 + n) * 64 + j] = __float2half(a);
        float vs = a * asj;
        float vd = a * adj;
#pragma unroll
        for (int o = 16; o; o >>= 1) {
            vs += __shfl_xor_sync(0xffffffffu, vs, o);
            vd += __shfl_xor_sync(0xffffffffu, vd, o);
        }
        if ((t & 31) == 0) { ps[n][w] = vs; pd[n][w] = vd; }
    }
    __syncthreads();
    if (t < 16) {
        g_as2[n0 + t] = ps[t][0] + ps[t][1];
        g_ad2[n0 + t] = pd[t][0] + pd[t][1];
    }
}

// ---------------- fused softmax aggregation (max-free, fp16 gather), layer 2 --
__global__ void __launch_bounds__(256) agg2_kernel(
        float* __restrict__ out, const float* __restrict__ b2) {
    int warp = threadIdx.x >> 5, lane = threadIdx.x & 31;
    int d = blockIdx.x * 8 + warp;
    int lo = g_row[d], hi = g_row[d + 1];
    float add = g_ad2[d];
    float s = 0.0f;
    float2 acc = make_float2(0, 0);
    int co = lane * 2;
    int i = lo;
    for (; i + 4 <= hi; i += 4) {
        int s0 = g_csrc[i], s1 = g_csrc[i + 1], s2 = g_csrc[i + 2], s3 = g_csrc[i + 3];
        float a0 = g_as2[s0], a1 = g_as2[s1], a2 = g_as2[s2], a3 = g_as2[s3];
        unsigned int r0 = *(const unsigned int*)&g_h2h[s0 * 64 + co];
        unsigned int r1 = *(const unsigned int*)&g_h2h[s1 * 64 + co];
        unsigned int r2 = *(const unsigned int*)&g_h2h[s2 * 64 + co];
        unsigned int r3 = *(const unsigned int*)&g_h2h[s3 * 64 + co];
        float w0 = __expf(lrelu(a0 + add));
        float w1 = __expf(lrelu(a1 + add));
        float w2 = __expf(lrelu(a2 + add));
        float w3 = __expf(lrelu(a3 + add));
        float2 h0 = __half22float2(*(__half2*)&r0);
        float2 h1 = __half22float2(*(__half2*)&r1);
        float2 h2 = __half22float2(*(__half2*)&r2);
        float2 h3 = __half22float2(*(__half2*)&r3);
        s += (w0 + w1) + (w2 + w3);
        acc.x = fmaf(w0, h0.x, acc.x); acc.y = fmaf(w0, h0.y, acc.y);
        acc.x = fmaf(w1, h1.x, acc.x); acc.y = fmaf(w1, h1.y, acc.y);
        acc.x = fmaf(w2, h2.x, acc.x); acc.y = fmaf(w2, h2.y, acc.y);
        acc.x = fmaf(w3, h3.x, acc.x); acc.y = fmaf(w3, h3.y, acc.y);
    }
    for (; i < hi; i++) {
        int sc = g_csrc[i];
        float w = __expf(lrelu(g_as2[sc] + add));
        unsigned int r = *(const unsigned int*)&g_h2h[sc * 64 + co];
        float2 hv = __half22float2(*(__half2*)&r);
        s += w;
        acc.x = fmaf(w, hv.x, acc.x);
        acc.y = fmaf(w, hv.y, acc.y);
    }
    float inv = 1.0f / (s + 1e-16f);
    float2 o;
    o.x = acc.x * inv + b2[co];
    o.y = acc.y * inv + b2[co + 1];
    *(float2*)&out[d * 64 + co] = o;
}

// ---------------- launch -------------------------------------------------------
extern "C" void kernel_launch(void* const* d_in, const int* in_sizes, int n_in,
                              void* d_out, int out_size) {
    const float* x   = (const float*)d_in[0];
    const void*  ei  = d_in[1];
    const float* W1  = (const float*)d_in[2];
    const float* as1 = (const float*)d_in[3];
    const float* ad1 = (const float*)d_in[4];
    const float* b1  = (const float*)d_in[5];
    const float* W2  = (const float*)d_in[6];
    const float* as2 = (const float*)d_in[7];
    const float* ad2 = (const float*)d_in[8];
    const float* b2  = (const float*)d_in[9];
    float*       out = (float*)d_out;

    const int TB = 256;
    auto nb = [](long long n, int tb) { return (int)((n + tb - 1) / tb); };

    // fork: gemm1 (x/W1 only) runs concurrently with the CSR build chain
    cudaStream_t s2;
    cudaStreamCreateWithFlags(&s2, cudaStreamNonBlocking);
    cudaEvent_t e1, e2;
    cudaEventCreateWithFlags(&e1, cudaEventDisableTiming);
    cudaEventCreateWithFlags(&e2, cudaEventDisableTiming);

    cudaEventRecord(e1, 0);
    cudaStreamWaitEvent(s2, e1, 0);
    gemm1_kernel<<<NN / 16, 128, 0, s2>>>(x, W1, as1, ad1);
    cudaEventRecord(e2, s2);

    zero_detect_kernel<<<SCAN_B, 256>>>(ei);
    convert_hist_kernel<<<nb(ET, TB), TB>>>(ei);
    scan1_kernel<<<SCAN_B, 256>>>();
    scan3_kernel<<<SCAN_B, 256>>>();
    scatter_kernel<<<nb(ET, TB), TB>>>();

    cudaStreamWaitEvent(0, e2, 0);
    agg1_kernel<<<NN / 8, 256>>>(b1);
    gemm2_kernel<<<NN / 16, 64>>>(W2, as2, ad2);
    agg2_kernel<<<NN / 8, 256>>>(out, b2);

    cudaEventDestroy(e1);
    cudaEventDestroy(e2);
    cudaStreamDestroy(s2);
}

// round 12
// speedup vs baseline: 1.3010x; 1.0273x over previous
#include <cuda_runtime.h>
#include <cuda_fp16.h>
#include <math.h>

#define NN 50000
#define EE 800000
#define ET (EE + NN)
#define F1 128
#define C2 64
#define NEG 0.2f

#define SCAN_B 196                       // ceil(50000/256)

// ---------------- scratch ----------------------------------------------------
__device__ int    g_is64;
__device__ int    g_src [ET];
__device__ int    g_dst [ET];
__device__ int    g_row [NN + 1];
__device__ int    g_wpos[NN];
__device__ int    g_bsum[SCAN_B];
__device__ int    g_csrc[ET];

__device__ __half g_h1h[NN * F1];          // layer1 features (fp16 gather)
__device__ float4 g_as1 [NN];
__device__ float4 g_ad1 [NN];

__device__ __half g_h2h[NN * C2];          // layer2 features (fp16 gather)
__device__ float  g_as2 [NN];
__device__ float  g_ad2 [NN];

__device__ __forceinline__ float lrelu(float v) { return v > 0.0f ? v : NEG * v; }

// ---------------- packed f32x2 helpers ----------------------------------------
__device__ __forceinline__ unsigned long long fma2(unsigned long long a,
                                                   unsigned long long b,
                                                   unsigned long long c) {
    unsigned long long d;
    asm("fma.rn.f32x2 %0, %1, %2, %3;" : "=l"(d) : "l"(a), "l"(b), "l"(c));
    return d;
}
__device__ __forceinline__ unsigned long long pack2(float lo, float hi) {
    unsigned long long r;
    asm("mov.b64 %0, {%1, %2};" : "=l"(r) : "f"(lo), "f"(hi));
    return r;
}
__device__ __forceinline__ float sum2(unsigned long long v) {
    float lo, hi;
    asm("mov.b64 {%0, %1}, %2;" : "=f"(lo), "=f"(hi) : "l"(v));
    return lo + hi;
}

// ---------------- zero counters + dtype detect ---------------------------------
__global__ void zero_detect_kernel(const void* __restrict__ ei) {
    int i = blockIdx.x * blockDim.x + threadIdx.x;
    if (i < NN) g_wpos[i] = 0;
    if (blockIdx.x == 0) {
        const unsigned long long* p = (const unsigned long long*)ei;
        int bad = (p[threadIdx.x] >= (unsigned long long)NN) ? 1 : 0;
        int anybad = __syncthreads_or(bad);
        if (threadIdx.x == 0) g_is64 = anybad ? 0 : 1;
    }
}

__global__ void convert_hist_kernel(const void* __restrict__ ei) {
    int e = blockIdx.x * blockDim.x + threadIdx.x;
    if (e >= ET) return;
    int s, d;
    if (e >= EE) s = d = e - EE;
    else if (g_is64) {
        s = (int)((const long long*)ei)[e];
        d = (int)((const long long*)ei)[EE + e];
    } else {
        s = ((const int*)ei)[e];
        d = ((const int*)ei)[EE + e];
    }
    g_src[e] = s;
    g_dst[e] = d;
    atomicAdd(&g_wpos[d], 1);
}

// ---------------- scan ----------------------------------------------------------
__device__ __forceinline__ int block_excl_scan(int v, int t, int* total) {
    __shared__ int wsum[8];
    int lane = t & 31, w = t >> 5;
    int inc = v;
#pragma unroll
    for (int o = 1; o < 32; o <<= 1) {
        int u = __shfl_up_sync(0xffffffffu, inc, o);
        if (lane >= o) inc += u;
    }
    if (lane == 31) wsum[w] = inc;
    __syncthreads();
    if (w == 0) {
        int ws = (lane < 8) ? wsum[lane] : 0;
#pragma unroll
        for (int o = 1; o < 8; o <<= 1) {
            int u = __shfl_up_sync(0xffffffffu, ws, o);
            if (lane >= o) ws += u;
        }
        if (lane < 8) wsum[lane] = ws;
    }
    __syncthreads();
    int base = (w > 0) ? wsum[w - 1] : 0;
    *total = wsum[7];
    return base + inc - v;
}

__global__ void scan1_kernel() {
    int t = threadIdx.x;
    int i = blockIdx.x * 256 + t;
    int v = (i < NN) ? g_wpos[i] : 0;
    int total;
    int ex = block_excl_scan(v, t, &total);
    if (i < NN) g_row[i] = ex;
    if (t == 0) g_bsum[blockIdx.x] = total;
}

__global__ void scan3_kernel() {
    __shared__ int ws[8];
    __shared__ int sbase;
    int t = threadIdx.x, b = blockIdx.x;
    int lane = t & 31, w = t >> 5;
    int v = (t < SCAN_B && t < b) ? g_bsum[t] : 0;
#pragma unroll
    for (int o = 16; o; o >>= 1) v += __shfl_xor_sync(0xffffffffu, v, o);
    if (lane == 0) ws[w] = v;
    __syncthreads();
    if (t == 0) {
        int tot = 0;
#pragma unroll
        for (int k = 0; k < 8; k++) tot += ws[k];
        sbase = tot;
    }
    __syncthreads();
    int i = b * 256 + t;
    if (i < NN) {
        int r = g_row[i] + sbase;
        g_row[i] = r;
        g_wpos[i] = r;
    }
    if (i == 0) g_row[NN] = ET;
}

__global__ void scatter_kernel() {
    int e = blockIdx.x * blockDim.x + threadIdx.x;
    if (e >= ET) return;
    int d = g_dst[e];
    int p = atomicAdd(&g_wpos[d], 1);
    g_csrc[p] = g_src[e];
}

// ---------------- gemm1 (FFMA2, 16 nodes/block, fp16 h1 out) -------------------
__global__ void __launch_bounds__(128) gemm1_kernel(
        const float* __restrict__ x, const float* __restrict__ W,
        const float* __restrict__ as, const float* __restrict__ ad) {
    __shared__ float xs[16][128];
    int n0 = blockIdx.x * 16;
    int t = threadIdx.x;
    const float4* x4 = (const float4*)(x + n0 * 128);
    float4* xs4 = (float4*)xs;
#pragma unroll
    for (int r = 0; r < 4; r++) xs4[t + r * 128] = x4[t + r * 128];
    __syncthreads();
    int j = t;
    unsigned long long acc2[16];
#pragma unroll
    for (int n = 0; n < 16; n++) acc2[n] = 0ull;
#pragma unroll
    for (int k = 0; k < 128; k += 4) {
        float w0 = W[(k + 0) * 128 + j];
        float w1 = W[(k + 1) * 128 + j];
        float w2 = W[(k + 2) * 128 + j];
        float w3 = W[(k + 3) * 128 + j];
        unsigned long long wp01 = pack2(w0, w1);
        unsigned long long wp23 = pack2(w2, w3);
#pragma unroll
        for (int n = 0; n < 16; n++) {
            float4 xv = *(const float4*)&xs[n][k];
            unsigned long long x01 = pack2(xv.x, xv.y);
            unsigned long long x23 = pack2(xv.z, xv.w);
            acc2[n] = fma2(x01, wp01, acc2[n]);
            acc2[n] = fma2(x23, wp23, acc2[n]);
        }
    }
    float asj = as[j], adj = ad[j];
    int h = j >> 5;
#pragma unroll
    for (int n = 0; n < 16; n++) {
        float a = sum2(acc2[n]);
        g_h1h[(n0 + n) * 128 + j] = __float2half(a);
        float vs = a * asj;
        float vd = a * adj;
#pragma unroll
        for (int o = 16; o; o >>= 1) {
            vs += __shfl_xor_sync(0xffffffffu, vs, o);
            vd += __shfl_xor_sync(0xffffffffu, vd, o);
        }
        if ((j & 31) == 0) {
            ((float*)&g_as1[n0 + n])[h] = vs;
            ((float*)&g_ad1[n0 + n])[h] = vd;
        }
    }
}

// ---------------- fused agg1 + gemm2 -------------------------------------------
// Phase A: warp-per-node softmax aggregation (8 nodes/block) -> h1e in smem.
// Phase B: block GEMM 8x64x128 (h2 = h1e @ W2) + alpha2 reductions.
__device__ __forceinline__ float4 h16x4_to_f4(uint2 raw) {
    __half2 p0 = *(__half2*)&raw.x;
    __half2 p1 = *(__half2*)&raw.y;
    float2 f0 = __half22float2(p0);
    float2 f1 = __half22float2(p1);
    return make_float4(f0.x, f0.y, f1.x, f1.y);
}

__global__ void __launch_bounds__(256) agg1_gemm2_kernel(
        const float* __restrict__ b1, const float* __restrict__ W2,
        const float* __restrict__ as2, const float* __restrict__ ad2) {
    __shared__ float xs[8][128];
    __shared__ float ps[8][2], pd[8][2];
    int t = threadIdx.x;
    int warp = t >> 5, lane = t & 31;
    int d0 = blockIdx.x * 8;
    int d = d0 + warp;

    // ---- Phase A: aggregation (identical math to R11 agg1) ----
    {
        int lo = g_row[d], hi = g_row[d + 1];
        int h = lane >> 3;
        float add = ((const float*)&g_ad1[d])[h];
        float s = 0.0f;
        float4 acc = make_float4(0, 0, 0, 0);
        int co = lane * 4;
        int i = lo;
        for (; i + 4 <= hi; i += 4) {
            int s0 = g_csrc[i], s1 = g_csrc[i + 1], s2 = g_csrc[i + 2], s3 = g_csrc[i + 3];
            float a0 = ((const float*)&g_as1[s0])[h];
            float a1 = ((const float*)&g_as1[s1])[h];
            float a2 = ((const float*)&g_as1[s2])[h];
            float a3 = ((const float*)&g_as1[s3])[h];
            uint2 r0 = *(const uint2*)&g_h1h[s0 * 128 + co];
            uint2 r1 = *(const uint2*)&g_h1h[s1 * 128 + co];
            uint2 r2 = *(const uint2*)&g_h1h[s2 * 128 + co];
            uint2 r3 = *(const uint2*)&g_h1h[s3 * 128 + co];
            float w0 = __expf(lrelu(a0 + add));
            float w1 = __expf(lrelu(a1 + add));
            float w2 = __expf(lrelu(a2 + add));
            float w3 = __expf(lrelu(a3 + add));
            float4 h0 = h16x4_to_f4(r0);
            float4 h1 = h16x4_to_f4(r1);
            float4 h2 = h16x4_to_f4(r2);
            float4 h3 = h16x4_to_f4(r3);
            s += (w0 + w1) + (w2 + w3);
            acc.x = fmaf(w0, h0.x, acc.x); acc.y = fmaf(w0, h0.y, acc.y);
            acc.z = fmaf(w0, h0.z, acc.z); acc.w = fmaf(w0, h0.w, acc.w);
            acc.x = fmaf(w1, h1.x, acc.x); acc.y = fmaf(w1, h1.y, acc.y);
            acc.z = fmaf(w1, h1.z, acc.z); acc.w = fmaf(w1, h1.w, acc.w);
            acc.x = fmaf(w2, h2.x, acc.x); acc.y = fmaf(w2, h2.y, acc.y);
            acc.z = fmaf(w2, h2.z, acc.z); acc.w = fmaf(w2, h2.w, acc.w);
            acc.x = fmaf(w3, h3.x, acc.x); acc.y = fmaf(w3, h3.y, acc.y);
            acc.z = fmaf(w3, h3.z, acc.z); acc.w = fmaf(w3, h3.w, acc.w);
        }
        for (; i < hi; i++) {
            int sc = g_csrc[i];
            float w = __expf(lrelu(((const float*)&g_as1[sc])[h] + add));
            float4 hv = h16x4_to_f4(*(const uint2*)&g_h1h[sc * 128 + co]);
            s += w;
            acc.x = fmaf(w, hv.x, acc.x); acc.y = fmaf(w, hv.y, acc.y);
            acc.z = fmaf(w, hv.z, acc.z); acc.w = fmaf(w, hv.w, acc.w);
        }
        float inv = 1.0f / (s + 1e-16f);
        float4 bv = *(const float4*)&b1[co];
        float4 o;
        o.x = acc.x * inv + bv.x;
        o.y = acc.y * inv + bv.y;
        o.z = acc.z * inv + bv.z;
        o.w = acc.w * inv + bv.w;
        o.x = o.x > 0.0f ? o.x : expm1f(o.x);
        o.y = o.y > 0.0f ? o.y : expm1f(o.y);
        o.z = o.z > 0.0f ? o.z : expm1f(o.z);
        o.w = o.w > 0.0f ? o.w : expm1f(o.w);
        *(float4*)&xs[warp][co] = o;
    }
    __syncthreads();

    // ---- Phase B: h2 = h1e @ W2 for the block's 8 nodes ----
    {
        int j = t & 63;                 // output column 0..63
        int g = t >> 6;                 // group 0..3, handles nodes 2g, 2g+1
        int nA = g * 2, nB = nA + 1;
        unsigned long long accA = 0ull, accB = 0ull;
#pragma unroll
        for (int k = 0; k < 128; k += 4) {
            float w0 = W2[(k + 0) * 64 + j];
            float w1 = W2[(k + 1) * 64 + j];
            float w2 = W2[(k + 2) * 64 + j];
            float w3 = W2[(k + 3) * 64 + j];
            unsigned long long wp01 = pack2(w0, w1);
            unsigned long long wp23 = pack2(w2, w3);
            float4 xa = *(const float4*)&xs[nA][k];
            float4 xb = *(const float4*)&xs[nB][k];
            accA = fma2(pack2(xa.x, xa.y), wp01, accA);
            accA = fma2(pack2(xa.z, xa.w), wp23, accA);
            accB = fma2(pack2(xb.x, xb.y), wp01, accB);
            accB = fma2(pack2(xb.z, xb.w), wp23, accB);
        }
        float aA = sum2(accA);
        float aB = sum2(accB);
        g_h2h[(d0 + nA) * 64 + j] = __float2half(aA);
        g_h2h[(d0 + nB) * 64 + j] = __float2half(aB);
        float asj = as2[j], adj = ad2[j];
        float vsA = aA * asj, vdA = aA * adj;
        float vsB = aB * asj, vdB = aB * adj;
#pragma unroll
        for (int o = 16; o; o >>= 1) {
            vsA += __shfl_xor_sync(0xffffffffu, vsA, o);
            vdA += __shfl_xor_sync(0xffffffffu, vdA, o);
            vsB += __shfl_xor_sync(0xffffffffu, vsB, o);
            vdB += __shfl_xor_sync(0xffffffffu, vdB, o);
        }
        int half = warp & 1;            // which 32-col half of node's 64 cols
        if (lane == 0) {
            ps[nA][half] = vsA; pd[nA][half] = vdA;
            ps[nB][half] = vsB; pd[nB][half] = vdB;
        }
    }
    __syncthreads();
    if (t < 8) {
        g_as2[d0 + t] = ps[t][0] + ps[t][1];
        g_ad2[d0 + t] = pd[t][0] + pd[t][1];
    }
}

// ---------------- fused softmax aggregation (max-free, fp16 gather), layer 2 --
__global__ void __launch_bounds__(256) agg2_kernel(
        float* __restrict__ out, const float* __restrict__ b2) {
    int warp = threadIdx.x >> 5, lane = threadIdx.x & 31;
    int d = blockIdx.x * 8 + warp;
    int lo = g_row[d], hi = g_row[d + 1];
    float add = g_ad2[d];
    float s = 0.0f;
    float2 acc = make_float2(0, 0);
    int co = lane * 2;
    int i = lo;
    for (; i + 4 <= hi; i += 4) {
        int s0 = g_csrc[i], s1 = g_csrc[i + 1], s2 = g_csrc[i + 2], s3 = g_csrc[i + 3];
        float a0 = g_as2[s0], a1 = g_as2[s1], a2 = g_as2[s2], a3 = g_as2[s3];
        unsigned int r0 = *(const unsigned int*)&g_h2h[s0 * 64 + co];
        unsigned int r1 = *(const unsigned int*)&g_h2h[s1 * 64 + co];
        unsigned int r2 = *(const unsigned int*)&g_h2h[s2 * 64 + co];
        unsigned int r3 = *(const unsigned int*)&g_h2h[s3 * 64 + co];
        float w0 = __expf(lrelu(a0 + add));
        float w1 = __expf(lrelu(a1 + add));
        float w2 = __expf(lrelu(a2 + add));
        float w3 = __expf(lrelu(a3 + add));
        float2 h0 = __half22float2(*(__half2*)&r0);
        float2 h1 = __half22float2(*(__half2*)&r1);
        float2 h2 = __half22float2(*(__half2*)&r2);
        float2 h3 = __half22float2(*(__half2*)&r3);
        s += (w0 + w1) + (w2 + w3);
        acc.x = fmaf(w0, h0.x, acc.x); acc.y = fmaf(w0, h0.y, acc.y);
        acc.x = fmaf(w1, h1.x, acc.x); acc.y = fmaf(w1, h1.y, acc.y);
        acc.x = fmaf(w2, h2.x, acc.x); acc.y = fmaf(w2, h2.y, acc.y);
        acc.x = fmaf(w3, h3.x, acc.x); acc.y = fmaf(w3, h3.y, acc.y);
    }
    for (; i < hi; i++) {
        int sc = g_csrc[i];
        float w = __expf(lrelu(g_as2[sc] + add));
        unsigned int r = *(const unsigned int*)&g_h2h[sc * 64 + co];
        float2 hv = __half22float2(*(__half2*)&r);
        s += w;
        acc.x = fmaf(w, hv.x, acc.x);
        acc.y = fmaf(w, hv.y, acc.y);
    }
    float inv = 1.0f / (s + 1e-16f);
    float2 o;
    o.x = acc.x * inv + b2[co];
    o.y = acc.y * inv + b2[co + 1];
    *(float2*)&out[d * 64 + co] = o;
}

// ---------------- launch -------------------------------------------------------
extern "C" void kernel_launch(void* const* d_in, const int* in_sizes, int n_in,
                              void* d_out, int out_size) {
    const float* x   = (const float*)d_in[0];
    const void*  ei  = d_in[1];
    const float* W1  = (const float*)d_in[2];
    const float* as1 = (const float*)d_in[3];
    const float* ad1 = (const float*)d_in[4];
    const float* b1  = (const float*)d_in[5];
    const float* W2  = (const float*)d_in[6];
    const float* as2 = (const float*)d_in[7];
    const float* ad2 = (const float*)d_in[8];
    const float* b2  = (const float*)d_in[9];
    float*       out = (float*)d_out;

    const int TB = 256;
    auto nb = [](long long n, int tb) { return (int)((n + tb - 1) / tb); };

    // fork: gemm1 (x/W1 only) runs concurrently with the CSR build chain
    cudaStream_t s2;
    cudaStreamCreateWithFlags(&s2, cudaStreamNonBlocking);
    cudaEvent_t e1, e2;
    cudaEventCreateWithFlags(&e1, cudaEventDisableTiming);
    cudaEventCreateWithFlags(&e2, cudaEventDisableTiming);

    cudaEventRecord(e1, 0);
    cudaStreamWaitEvent(s2, e1, 0);
    gemm1_kernel<<<NN / 16, 128, 0, s2>>>(x, W1, as1, ad1);
    cudaEventRecord(e2, s2);

    zero_detect_kernel<<<SCAN_B, 256>>>(ei);
    convert_hist_kernel<<<nb(ET, TB), TB>>>(ei);
    scan1_kernel<<<SCAN_B, 256>>>();
    scan3_kernel<<<SCAN_B, 256>>>();
    scatter_kernel<<<nb(ET, TB), TB>>>();

    cudaStreamWaitEvent(0, e2, 0);
    agg1_gemm2_kernel<<<NN / 8, 256>>>(b1, W2, as2, ad2);
    agg2_kernel<<<NN / 8, 256>>>(out, b2);

    cudaEventDestroy(e1);
    cudaEventDestroy(e2);
    cudaStreamDestroy(s2);
}

// round 13
// speedup vs baseline: 1.3244x; 1.0180x over previous
#include <cuda_runtime.h>
#include <cuda_fp16.h>
#include <math.h>

#define NN 50000
#define EE 800000
#define ET (EE + NN)
#define F1 128
#define C2 64
#define NEG 0.2f

#define SCAN_B 196                       // ceil(50000/256)

// ---------------- scratch ----------------------------------------------------
__device__ int    g_is64;
__device__ int    g_src [ET];
__device__ int    g_dst [ET];
__device__ int    g_row [NN + 1];
__device__ int    g_wpos[NN];
__device__ int    g_bsum[SCAN_B];
__device__ int    g_csrc[ET];

__device__ __half g_h1h[NN * F1];          // layer1 features (fp16 gather)
__device__ float4 g_as1 [NN];
__device__ float4 g_ad1 [NN];

__device__ __half g_h2h[NN * C2];          // layer2 features (fp16 gather)
__device__ float  g_as2 [NN];
__device__ float  g_ad2 [NN];

__device__ __forceinline__ float lrelu(float v) { return v > 0.0f ? v : NEG * v; }

// ---------------- packed f32x2 helpers ----------------------------------------
__device__ __forceinline__ unsigned long long fma2(unsigned long long a,
                                                   unsigned long long b,
                                                   unsigned long long c) {
    unsigned long long d;
    asm("fma.rn.f32x2 %0, %1, %2, %3;" : "=l"(d) : "l"(a), "l"(b), "l"(c));
    return d;
}
__device__ __forceinline__ unsigned long long pack2(float lo, float hi) {
    unsigned long long r;
    asm("mov.b64 %0, {%1, %2};" : "=l"(r) : "f"(lo), "f"(hi));
    return r;
}
__device__ __forceinline__ float sum2(unsigned long long v) {
    float lo, hi;
    asm("mov.b64 {%0, %1}, %2;" : "=f"(lo), "=f"(hi) : "l"(v));
    return lo + hi;
}

// ---------------- zero counters + dtype detect ---------------------------------
__global__ void zero_detect_kernel(const void* __restrict__ ei) {
    int i = blockIdx.x * blockDim.x + threadIdx.x;
    if (i < NN) g_wpos[i] = 0;
    if (blockIdx.x == 0) {
        const unsigned long long* p = (const unsigned long long*)ei;
        int bad = (p[threadIdx.x] >= (unsigned long long)NN) ? 1 : 0;
        int anybad = __syncthreads_or(bad);
        if (threadIdx.x == 0) g_is64 = anybad ? 0 : 1;
    }
}

__global__ void convert_hist_kernel(const void* __restrict__ ei) {
    int e = blockIdx.x * blockDim.x + threadIdx.x;
    if (e >= ET) return;
    int s, d;
    if (e >= EE) s = d = e - EE;
    else if (g_is64) {
        s = (int)((const long long*)ei)[e];
        d = (int)((const long long*)ei)[EE + e];
    } else {
        s = ((const int*)ei)[e];
        d = ((const int*)ei)[EE + e];
    }
    g_src[e] = s;
    g_dst[e] = d;
    atomicAdd(&g_wpos[d], 1);
}

// ---------------- scan ----------------------------------------------------------
__device__ __forceinline__ int block_excl_scan(int v, int t, int* total) {
    __shared__ int wsum[8];
    int lane = t & 31, w = t >> 5;
    int inc = v;
#pragma unroll
    for (int o = 1; o < 32; o <<= 1) {
        int u = __shfl_up_sync(0xffffffffu, inc, o);
        if (lane >= o) inc += u;
    }
    if (lane == 31) wsum[w] = inc;
    __syncthreads();
    if (w == 0) {
        int ws = (lane < 8) ? wsum[lane] : 0;
#pragma unroll
        for (int o = 1; o < 8; o <<= 1) {
            int u = __shfl_up_sync(0xffffffffu, ws, o);
            if (lane >= o) ws += u;
        }
        if (lane < 8) wsum[lane] = ws;
    }
    __syncthreads();
    int base = (w > 0) ? wsum[w - 1] : 0;
    *total = wsum[7];
    return base + inc - v;
}

__global__ void scan1_kernel() {
    int t = threadIdx.x;
    int i = blockIdx.x * 256 + t;
    int v = (i < NN) ? g_wpos[i] : 0;
    int total;
    int ex = block_excl_scan(v, t, &total);
    if (i < NN) g_row[i] = ex;
    if (t == 0) g_bsum[blockIdx.x] = total;
}

__global__ void scan3_kernel() {
    __shared__ int ws[8];
    __shared__ int sbase;
    int t = threadIdx.x, b = blockIdx.x;
    int lane = t & 31, w = t >> 5;
    int v = (t < SCAN_B && t < b) ? g_bsum[t] : 0;
#pragma unroll
    for (int o = 16; o; o >>= 1) v += __shfl_xor_sync(0xffffffffu, v, o);
    if (lane == 0) ws[w] = v;
    __syncthreads();
    if (t == 0) {
        int tot = 0;
#pragma unroll
        for (int k = 0; k < 8; k++) tot += ws[k];
        sbase = tot;
    }
    __syncthreads();
    int i = b * 256 + t;
    if (i < NN) {
        int r = g_row[i] + sbase;
        g_row[i] = r;
        g_wpos[i] = r;
    }
    if (i == 0) g_row[NN] = ET;
}

__global__ void scatter_kernel() {
    int e = blockIdx.x * blockDim.x + threadIdx.x;
    if (e >= ET) return;
    int d = g_dst[e];
    int p = atomicAdd(&g_wpos[d], 1);
    g_csrc[p] = g_src[e];
}

// ---------------- gemm1 (FFMA2, 16 nodes/block, fp16 h1 out) -------------------
__global__ void __launch_bounds__(128) gemm1_kernel(
        const float* __restrict__ x, const float* __restrict__ W,
        const float* __restrict__ as, const float* __restrict__ ad) {
    __shared__ float xs[16][128];
    int n0 = blockIdx.x * 16;
    int t = threadIdx.x;
    const float4* x4 = (const float4*)(x + n0 * 128);
    float4* xs4 = (float4*)xs;
#pragma unroll
    for (int r = 0; r < 4; r++) xs4[t + r * 128] = x4[t + r * 128];
    __syncthreads();
    int j = t;
    unsigned long long acc2[16];
#pragma unroll
    for (int n = 0; n < 16; n++) acc2[n] = 0ull;
#pragma unroll
    for (int k = 0; k < 128; k += 4) {
        float w0 = W[(k + 0) * 128 + j];
        float w1 = W[(k + 1) * 128 + j];
        float w2 = W[(k + 2) * 128 + j];
        float w3 = W[(k + 3) * 128 + j];
        unsigned long long wp01 = pack2(w0, w1);
        unsigned long long wp23 = pack2(w2, w3);
#pragma unroll
        for (int n = 0; n < 16; n++) {
            float4 xv = *(const float4*)&xs[n][k];
            unsigned long long x01 = pack2(xv.x, xv.y);
            unsigned long long x23 = pack2(xv.z, xv.w);
            acc2[n] = fma2(x01, wp01, acc2[n]);
            acc2[n] = fma2(x23, wp23, acc2[n]);
        }
    }
    float asj = as[j], adj = ad[j];
    int h = j >> 5;
#pragma unroll
    for (int n = 0; n < 16; n++) {
        float a = sum2(acc2[n]);
        g_h1h[(n0 + n) * 128 + j] = __float2half(a);
        float vs = a * asj;
        float vd = a * adj;
#pragma unroll
        for (int o = 16; o; o >>= 1) {
            vs += __shfl_xor_sync(0xffffffffu, vs, o);
            vd += __shfl_xor_sync(0xffffffffu, vd, o);
        }
        if ((j & 31) == 0) {
            ((float*)&g_as1[n0 + n])[h] = vs;
            ((float*)&g_ad1[n0 + n])[h] = vd;
        }
    }
}

// ---------------- fused agg1 + gemm2 (8-deep gather pipeline) -------------------
__device__ __forceinline__ float4 h16x4_to_f4(uint2 raw) {
    __half2 p0 = *(__half2*)&raw.x;
    __half2 p1 = *(__half2*)&raw.y;
    float2 f0 = __half22float2(p0);
    float2 f1 = __half22float2(p1);
    return make_float4(f0.x, f0.y, f1.x, f1.y);
}

__global__ void __launch_bounds__(256) agg1_gemm2_kernel(
        const float* __restrict__ b1, const float* __restrict__ W2,
        const float* __restrict__ as2, const float* __restrict__ ad2) {
    __shared__ float xs[8][128];
    __shared__ float ps[8][2], pd[8][2];
    int t = threadIdx.x;
    int warp = t >> 5, lane = t & 31;
    int d0 = blockIdx.x * 8;
    int d = d0 + warp;

    // ---- Phase A: aggregation, 8 edges in flight ----
    {
        int lo = g_row[d], hi = g_row[d + 1];
        int h = lane >> 3;
        float add = ((const float*)&g_ad1[d])[h];
        float s = 0.0f;
        float4 acc = make_float4(0, 0, 0, 0);
        int co = lane * 4;
        int i = lo;
        for (; i + 8 <= hi; i += 8) {
            int sc[8];
#pragma unroll
            for (int u = 0; u < 8; u++) sc[u] = g_csrc[i + u];
            uint2 r[8];
#pragma unroll
            for (int u = 0; u < 8; u++) r[u] = *(const uint2*)&g_h1h[sc[u] * 128 + co];
            float a[8];
#pragma unroll
            for (int u = 0; u < 8; u++) a[u] = ((const float*)&g_as1[sc[u]])[h];
#pragma unroll
            for (int u = 0; u < 8; u++) {
                float w = __expf(lrelu(a[u] + add));
                float4 hv = h16x4_to_f4(r[u]);
                s += w;
                acc.x = fmaf(w, hv.x, acc.x); acc.y = fmaf(w, hv.y, acc.y);
                acc.z = fmaf(w, hv.z, acc.z); acc.w = fmaf(w, hv.w, acc.w);
            }
        }
        for (; i < hi; i++) {
            int sc = g_csrc[i];
            float w = __expf(lrelu(((const float*)&g_as1[sc])[h] + add));
            float4 hv = h16x4_to_f4(*(const uint2*)&g_h1h[sc * 128 + co]);
            s += w;
            acc.x = fmaf(w, hv.x, acc.x); acc.y = fmaf(w, hv.y, acc.y);
            acc.z = fmaf(w, hv.z, acc.z); acc.w = fmaf(w, hv.w, acc.w);
        }
        float inv = 1.0f / (s + 1e-16f);
        float4 bv = *(const float4*)&b1[co];
        float4 o;
        o.x = acc.x * inv + bv.x;
        o.y = acc.y * inv + bv.y;
        o.z = acc.z * inv + bv.z;
        o.w = acc.w * inv + bv.w;
        o.x = o.x > 0.0f ? o.x : __expf(o.x) - 1.0f;
        o.y = o.y > 0.0f ? o.y : __expf(o.y) - 1.0f;
        o.z = o.z > 0.0f ? o.z : __expf(o.z) - 1.0f;
        o.w = o.w > 0.0f ? o.w : __expf(o.w) - 1.0f;
        *(float4*)&xs[warp][co] = o;
    }
    __syncthreads();

    // ---- Phase B: h2 = h1e @ W2 for the block's 8 nodes ----
    {
        int j = t & 63;
        int g = t >> 6;
        int nA = g * 2, nB = nA + 1;
        unsigned long long accA = 0ull, accB = 0ull;
#pragma unroll
        for (int k = 0; k < 128; k += 4) {
            float w0 = W2[(k + 0) * 64 + j];
            float w1 = W2[(k + 1) * 64 + j];
            float w2 = W2[(k + 2) * 64 + j];
            float w3 = W2[(k + 3) * 64 + j];
            unsigned long long wp01 = pack2(w0, w1);
            unsigned long long wp23 = pack2(w2, w3);
            float4 xa = *(const float4*)&xs[nA][k];
            float4 xb = *(const float4*)&xs[nB][k];
            accA = fma2(pack2(xa.x, xa.y), wp01, accA);
            accA = fma2(pack2(xa.z, xa.w), wp23, accA);
            accB = fma2(pack2(xb.x, xb.y), wp01, accB);
            accB = fma2(pack2(xb.z, xb.w), wp23, accB);
        }
        float aA = sum2(accA);
        float aB = sum2(accB);
        g_h2h[(d0 + nA) * 64 + j] = __float2half(aA);
        g_h2h[(d0 + nB) * 64 + j] = __float2half(aB);
        float asj = as2[j], adj = ad2[j];
        float vsA = aA * asj, vdA = aA * adj;
        float vsB = aB * asj, vdB = aB * adj;
#pragma unroll
        for (int o = 16; o; o >>= 1) {
            vsA += __shfl_xor_sync(0xffffffffu, vsA, o);
            vdA += __shfl_xor_sync(0xffffffffu, vdA, o);
            vsB += __shfl_xor_sync(0xffffffffu, vsB, o);
            vdB += __shfl_xor_sync(0xffffffffu, vdB, o);
        }
        int half = warp & 1;
        if (lane == 0) {
            ps[nA][half] = vsA; pd[nA][half] = vdA;
            ps[nB][half] = vsB; pd[nB][half] = vdB;
        }
    }
    __syncthreads();
    if (t < 8) {
        g_as2[d0 + t] = ps[t][0] + ps[t][1];
        g_ad2[d0 + t] = pd[t][0] + pd[t][1];
    }
}

// ---------------- agg2 (8-deep gather pipeline) ---------------------------------
__global__ void __launch_bounds__(256) agg2_kernel(
        float* __restrict__ out, const float* __restrict__ b2) {
    int warp = threadIdx.x >> 5, lane = threadIdx.x & 31;
    int d = blockIdx.x * 8 + warp;
    int lo = g_row[d], hi = g_row[d + 1];
    float add = g_ad2[d];
    float s = 0.0f;
    float2 acc = make_float2(0, 0);
    int co = lane * 2;
    int i = lo;
    for (; i + 8 <= hi; i += 8) {
        int sc[8];
#pragma unroll
        for (int u = 0; u < 8; u++) sc[u] = g_csrc[i + u];
        unsigned int r[8];
#pragma unroll
        for (int u = 0; u < 8; u++) r[u] = *(const unsigned int*)&g_h2h[sc[u] * 64 + co];
        float a[8];
#pragma unroll
        for (int u = 0; u < 8; u++) a[u] = g_as2[sc[u]];
#pragma unroll
        for (int u = 0; u < 8; u++) {
            float w = __expf(lrelu(a[u] + add));
            float2 hv = __half22float2(*(__half2*)&r[u]);
            s += w;
            acc.x = fmaf(w, hv.x, acc.x);
            acc.y = fmaf(w, hv.y, acc.y);
        }
    }
    for (; i < hi; i++) {
        int sc = g_csrc[i];
        float w = __expf(lrelu(g_as2[sc] + add));
        unsigned int r = *(const unsigned int*)&g_h2h[sc * 64 + co];
        float2 hv = __half22float2(*(__half2*)&r);
        s += w;
        acc.x = fmaf(w, hv.x, acc.x);
        acc.y = fmaf(w, hv.y, acc.y);
    }
    float inv = 1.0f / (s + 1e-16f);
    float2 o;
    o.x = acc.x * inv + b2[co];
    o.y = acc.y * inv + b2[co + 1];
    *(float2*)&out[d * 64 + co] = o;
}

// ---------------- launch -------------------------------------------------------
extern "C" void kernel_launch(void* const* d_in, const int* in_sizes, int n_in,
                              void* d_out, int out_size) {
    const float* x   = (const float*)d_in[0];
    const void*  ei  = d_in[1];
    const float* W1  = (const float*)d_in[2];
    const float* as1 = (const float*)d_in[3];
    const float* ad1 = (const float*)d_in[4];
    const float* b1  = (const float*)d_in[5];
    const float* W2  = (const float*)d_in[6];
    const float* as2 = (const float*)d_in[7];
    const float* ad2 = (const float*)d_in[8];
    const float* b2  = (const float*)d_in[9];
    float*       out = (float*)d_out;

    const int TB = 256;
    auto nb = [](long long n, int tb) { return (int)((n + tb - 1) / tb); };

    // fork: gemm1 (x/W1 only) runs concurrently with the CSR build chain
    cudaStream_t s2;
    cudaStreamCreateWithFlags(&s2, cudaStreamNonBlocking);
    cudaEvent_t e1, e2;
    cudaEventCreateWithFlags(&e1, cudaEventDisableTiming);
    cudaEventCreateWithFlags(&e2, cudaEventDisableTiming);

    cudaEventRecord(e1, 0);
    cudaStreamWaitEvent(s2, e1, 0);
    gemm1_kernel<<<NN / 16, 128, 0, s2>>>(x, W1, as1, ad1);
    cudaEventRecord(e2, s2);

    zero_detect_kernel<<<SCAN_B, 256>>>(ei);
    convert_hist_kernel<<<nb(ET, TB), TB>>>(ei);
    scan1_kernel<<<SCAN_B, 256>>>();
    scan3_kernel<<<SCAN_B, 256>>>();
    scatter_kernel<<<nb(ET, TB), TB>>>();

    cudaStreamWaitEvent(0, e2, 0);
    agg1_gemm2_kernel<<<NN / 8, 256>>>(b1, W2, as2, ad2);
    agg2_kernel<<<NN / 8, 256>>>(out, b2);

    cudaEventDestroy(e1);
    cudaEventDestroy(e2);
    cudaStreamDestroy(s2);
}